// round 9
// baseline (speedup 1.0000x reference)
#include <cuda_runtime.h>
#include <cuda_fp16.h>
#include <math.h>
#include <stdint.h>

// Problem constants
#define BB 16
#define PP 512
#define DD 1024
#define WW 400
#define TT 32
#define EE 64
#define HH 600
#define NPAIR (TT * EE)     // 2048
#define KF 4096             // W0T row length
#define KPOFF 2048          // pair-GEMM feature base: [t*e | |t-e|]
#define KP 2048             // pair-GEMM K
#define NPAD 640
#define KC 64               // k per chunk
#define NCHUNK 32           // KP / KC
#define NTILES 5            // h tiles of 128

// smem geometry (bytes): stage = A[128][64h] + B[128][64h], pitch 144
#define PITCH 144
#define B_OFF (128 * PITCH)               // 18432
#define STAGE_BYTES (2 * 128 * PITCH)     // 36864
#define NSTAGE 3
#define SMEM_DYN (NSTAGE * STAGE_BYTES)   // 110592

// ---------------- scratch ----------------------------------------------------
__device__ float g_word[(size_t)BB * WW * DD];
__device__ float g_trig[(size_t)BB * TT * DD];
__device__ float g_ent [(size_t)BB * EE * DD];
__device__ __half g_W0T[(size_t)NPAD * KF];            // W0^T fp16 [n][k]
__device__ __half g_A  [(size_t)BB * NPAIR * KP];      // pair features fp16 (134MB)
__device__ float g_Pt [(size_t)BB * TT * NPAD];
__device__ float g_Pe [(size_t)BB * EE * NPAD];
__device__ float g_part[(size_t)NTILES * BB * NPAIR * 2];

// ---------------- helpers ----------------------------------------------------
__device__ __forceinline__ void mma16816(float* c, const uint32_t* a, const uint32_t* b) {
    asm volatile(
        "mma.sync.aligned.m16n8k16.row.col.f32.f16.f16.f32 "
        "{%0,%1,%2,%3}, {%4,%5,%6,%7}, {%8,%9}, {%0,%1,%2,%3};"
        : "+f"(c[0]), "+f"(c[1]), "+f"(c[2]), "+f"(c[3])
        : "r"(a[0]), "r"(a[1]), "r"(a[2]), "r"(a[3]), "r"(b[0]), "r"(b[1]));
}
__device__ __forceinline__ void ldm_x4(uint32_t* r, uint32_t addr) {
    asm volatile("ldmatrix.sync.aligned.m8n8.x4.shared.b16 {%0,%1,%2,%3}, [%4];"
                 : "=r"(r[0]), "=r"(r[1]), "=r"(r[2]), "=r"(r[3]) : "r"(addr));
}
__device__ __forceinline__ void ldm_x2(uint32_t* r, uint32_t addr) {
    asm volatile("ldmatrix.sync.aligned.m8n8.x2.shared.b16 {%0,%1}, [%2];"
                 : "=r"(r[0]), "=r"(r[1]) : "r"(addr));
}
__device__ __forceinline__ void cp16(uint32_t dst, const void* src) {
    asm volatile("cp.async.ca.shared.global [%0], [%1], 16;" :: "r"(dst), "l"(src) : "memory");
}
__device__ __forceinline__ uint32_t smem_u32(const void* p) {
    uint32_t a;
    asm("{ .reg .u64 t; cvta.to.shared.u64 t, %1; cvt.u32.u64 %0, t; }"
        : "=r"(a) : "l"(p));
    return a;
}
__device__ __forceinline__ uint32_t pack_h2(float lo, float hi) {
    uint32_t r;
    asm("cvt.rn.f16x2.f32 %0, %1, %2;" : "=r"(r) : "f"(hi), "f"(lo));
    return r;
}

// ---------------- kernel 1: wordpiece -> word mean ---------------------------
__global__ void word_mean_kernel(const float* __restrict__ piece,
                                 const int* __restrict__ widx,
                                 float* __restrict__ out) {
    int w = blockIdx.x, b = blockIdx.y;
    int s = widx[(b * WW + w) * 2];
    int e = widx[(b * WW + w) * 2 + 1];
    float inv = 1.0f / (float)(e - s);
    const float* base = piece + (size_t)b * PP * DD;
    int t = threadIdx.x;
    float a0 = 0.f, a1 = 0.f, a2 = 0.f, a3 = 0.f;
    for (int r = s; r < e; r++) {
        float4 v = ((const float4*)(base + (size_t)r * DD))[t];
        a0 += v.x; a1 += v.y; a2 += v.z; a3 += v.w;
    }
    float4 o = make_float4(a0 * inv, a1 * inv, a2 * inv, a3 * inv);
    ((float4*)(out + (size_t)(b * WW + w) * DD))[t] = o;
}

// ---------------- kernel 2: word -> span means (trig + ent fused) ------------
__global__ void spans_kernel(const float* __restrict__ words,
                             const int* __restrict__ tidx,
                             const int* __restrict__ eidx,
                             float* __restrict__ trig,
                             float* __restrict__ ent) {
    int m = blockIdx.x, b = blockIdx.y;
    const int* idx;
    float* out;
    int mm, M;
    if (m < TT) { idx = tidx; out = trig; mm = m; M = TT; }
    else        { idx = eidx; out = ent;  mm = m - TT; M = EE; }
    int s = idx[(b * M + mm) * 2];
    int e = idx[(b * M + mm) * 2 + 1];
    float inv = 1.0f / (float)(e - s);
    const float* base = words + (size_t)b * WW * DD;
    int t = threadIdx.x;
    float a0 = 0.f, a1 = 0.f, a2 = 0.f, a3 = 0.f;
    for (int r = s; r < e; r++) {
        float4 v = ((const float4*)(base + (size_t)r * DD))[t];
        a0 += v.x; a1 += v.y; a2 += v.z; a3 += v.w;
    }
    float4 o = make_float4(a0 * inv, a1 * inv, a2 * inv, a3 * inv);
    ((float4*)(out + (size_t)(b * M + mm) * DD))[t] = o;
}

// ---------------- kernel 3: W0 [k][HH] -> W0T fp16 [NPAD][KF] ----------------
__global__ void bprep_kernel(const float* __restrict__ W0,
                             __half* __restrict__ W0T) {
    __shared__ float tile[32][33];
    int k0 = blockIdx.x * 32, n0 = blockIdx.y * 32;
    int x = threadIdx.x, y = threadIdx.y;
    float v = 0.f;
    if (n0 + x < HH) v = W0[(size_t)(k0 + y) * HH + (n0 + x)];
    tile[y][x] = v;
    __syncthreads();
    float w = tile[x][y];
    W0T[(size_t)(n0 + y) * KF + (k0 + x)] = __float2half_rn(w);
}

// ---------------- kernel 3c: A-gen: pair features fp16 -----------------------
__global__ void agen_kernel(const float* __restrict__ trig,
                            const float* __restrict__ ent,
                            __half* __restrict__ A) {
    int pair = blockIdx.x, b = blockIdx.y;
    int t = pair >> 6, e = pair & 63;
    int tid = threadIdx.x;
    const float4* tr = (const float4*)(trig + ((size_t)b * TT + t) * DD + tid * 8);
    const float4* er = (const float4*)(ent  + ((size_t)b * EE + e) * DD + tid * 8);
    float4 t0 = tr[0], t1 = tr[1];
    float4 e0 = er[0], e1 = er[1];
    size_t rowo = ((size_t)b * NPAIR + pair) * KP;
    uint4 p;
    p.x = pack_h2(t0.x * e0.x, t0.y * e0.y);
    p.y = pack_h2(t0.z * e0.z, t0.w * e0.w);
    p.z = pack_h2(t1.x * e1.x, t1.y * e1.y);
    p.w = pack_h2(t1.z * e1.z, t1.w * e1.w);
    *(uint4*)(A + rowo + tid * 8) = p;
    uint4 d;
    d.x = pack_h2(fabsf(t0.x - e0.x), fabsf(t0.y - e0.y));
    d.y = pack_h2(fabsf(t0.z - e0.z), fabsf(t0.w - e0.w));
    d.z = pack_h2(fabsf(t1.x - e1.x), fabsf(t1.y - e1.y));
    d.w = pack_h2(fabsf(t1.z - e1.z), fabsf(t1.w - e1.w));
    *(uint4*)(A + rowo + 1024 + tid * 8) = d;
}

// ---------------- kernel 3b: combined P GEMM (Pt + Pe in one launch) ---------
__global__ __launch_bounds__(256)
void pgemm_kernel(const float* __restrict__ trig,
                  const float* __restrict__ ent,
                  const __half* __restrict__ W0T,
                  const float* __restrict__ b0,
                  float* __restrict__ Pt,
                  float* __restrict__ Pe) {
    __shared__ char psm[STAGE_BYTES];
    uint32_t sb = smem_u32(psm);
    int tid = threadIdx.x;
    int lane = tid & 31, warp = tid >> 5;
    int wm = warp >> 2, wn = warp & 3;
    int g = lane >> 2, t2 = (lane & 3) * 2;
    int nt = blockIdx.x, mtg = blockIdx.y;
    int n0 = nt * 128;

    const float* X;
    float* C;
    const float* bias;
    int m0, koff;
    if (mtg < 4) { X = trig; C = Pt; bias = b0;      m0 = mtg * 128;       koff = 0;  }
    else         { X = ent;  C = Pe; bias = nullptr; m0 = (mtg - 4) * 128; koff = DD; }

    int prow = tid >> 1;
    int cb = (tid & 1) * 32;
    const float* xrow = X + (size_t)(m0 + prow) * DD;
    uint32_t aDst = sb + (uint32_t)prow * PITCH + cb * 2;
    uint32_t bDst = sb + B_OFF + (uint32_t)prow * PITCH + cb * 2;
    const __half* bSrcBase = W0T + (size_t)(n0 + prow) * KF + koff + cb;

    uint32_t aLd = sb + (uint32_t)(wm * 64 + g) * PITCH + (uint32_t)t2 * 2;
    uint32_t bLd = sb + B_OFF + (uint32_t)(wn * 32 + g) * PITCH + (uint32_t)t2 * 2;

    float acc[4][4][4];
#pragma unroll
    for (int i = 0; i < 4; i++)
#pragma unroll
        for (int j = 0; j < 4; j++)
#pragma unroll
            for (int q = 0; q < 4; q++) acc[i][j][q] = 0.f;

    for (int c = 0; c < DD / KC; c++) {
        float xv[32];
#pragma unroll
        for (int q = 0; q < 8; q++) {
            float4 v = ((const float4*)(xrow + c * KC + cb))[q];
            xv[q*4+0] = v.x; xv[q*4+1] = v.y; xv[q*4+2] = v.z; xv[q*4+3] = v.w;
        }
        const char* bs = (const char*)(bSrcBase + c * KC);
#pragma unroll
        for (int q = 0; q < 4; q++)
            cp16(bDst + q * 16, bs + q * 16);
#pragma unroll
        for (int gq = 0; gq < 4; gq++) {
            uint32_t p0 = pack_h2(xv[gq*8+0], xv[gq*8+1]);
            uint32_t p1 = pack_h2(xv[gq*8+2], xv[gq*8+3]);
            uint32_t p2 = pack_h2(xv[gq*8+4], xv[gq*8+5]);
            uint32_t p3 = pack_h2(xv[gq*8+6], xv[gq*8+7]);
            asm volatile("st.shared.v4.b32 [%0], {%1,%2,%3,%4};"
                         :: "r"(aDst + gq * 16), "r"(p0), "r"(p1), "r"(p2), "r"(p3) : "memory");
        }
        asm volatile("cp.async.wait_all;" ::: "memory");
        __syncthreads();
#pragma unroll
        for (int ks = 0; ks < 4; ks++) {
            uint32_t afr[4][4], bfr[4][2];
            uint32_t aO = aLd + (uint32_t)ks * 32;
            uint32_t bO = bLd + (uint32_t)ks * 32;
#pragma unroll
            for (int j = 0; j < 4; j++) {
                uint32_t o = bO + (uint32_t)j * (8 * PITCH);
                asm volatile("ld.shared.b32 %0, [%1];" : "=r"(bfr[j][0]) : "r"(o));
                asm volatile("ld.shared.b32 %0, [%1];" : "=r"(bfr[j][1]) : "r"(o + 16));
            }
#pragma unroll
            for (int i = 0; i < 4; i++) {
                uint32_t o = aO + (uint32_t)i * (16 * PITCH);
                asm volatile("ld.shared.b32 %0, [%1];" : "=r"(afr[i][0]) : "r"(o));
                asm volatile("ld.shared.b32 %0, [%1];" : "=r"(afr[i][1]) : "r"(o + 8 * PITCH));
                asm volatile("ld.shared.b32 %0, [%1];" : "=r"(afr[i][2]) : "r"(o + 16));
                asm volatile("ld.shared.b32 %0, [%1];" : "=r"(afr[i][3]) : "r"(o + 8 * PITCH + 16));
            }
#pragma unroll
            for (int i = 0; i < 4; i++)
#pragma unroll
                for (int j = 0; j < 4; j++)
                    mma16816(acc[i][j], afr[i], bfr[j]);
        }
        __syncthreads();
    }

#pragma unroll
    for (int j = 0; j < 4; j++) {
        int hcol = n0 + wn * 32 + j * 8 + t2;
#pragma unroll
        for (int cp = 0; cp < 2; cp++) {
            int h = hcol + cp;
            float bb = (bias && h < HH) ? bias[h] : 0.f;
#pragma unroll
            for (int i = 0; i < 4; i++) {
                int r0 = m0 + wm * 64 + i * 16 + g;
                C[(size_t)r0 * NPAD + h]       = acc[i][j][cp] + bb;
                C[(size_t)(r0 + 8) * NPAD + h] = acc[i][j][2 + cp] + bb;
            }
        }
    }
}

// ---------------- kernel 4: pair GEMM (ldmatrix + strided-j n-trim) ----------
// grid (NTILES, 256): x=nt fastest (L2 A reuse). 2 CTAs/SM, 3-stage cp.async.
// Warp cols: n0 + j*32 + wn*8 (strided groups -> last-tile trim balanced
// across SMSPs). Epilogue: acc + Pt + Pe, relu, @W1 -> per-ntile partials.
__global__ __launch_bounds__(256, 2)
void pair_mma_kernel(const __half* __restrict__ A,
                     const __half* __restrict__ W0T,
                     const float* __restrict__ Pt,
                     const float* __restrict__ Pe,
                     const float* __restrict__ W1,
                     float* __restrict__ part) {
    extern __shared__ char dsm[];
    uint32_t sb = smem_u32(dsm);
    int tid = threadIdx.x;
    int lane = tid & 31, warp = tid >> 5;
    int wm = warp >> 2, wn = warp & 3;
    int g = lane >> 2, t2 = (lane & 3) * 2;
    int nt = blockIdx.x, mtb = blockIdx.y;
    int b = mtb >> 4, mt = mtb & 15;
    int n0 = nt * 128;

    // producer source/dst
    int prow = tid >> 1, pseg = tid & 1;
    const char* aSrc = (const char*)A + ((size_t)mtb * 128 + prow) * (KP * 2) + pseg * 64;
    const char* bSrc = (const char*)W0T + ((size_t)(n0 + prow) * KF + KPOFF) * 2 + pseg * 64;
    uint32_t aDst = sb + (uint32_t)prow * PITCH + pseg * 64;
    uint32_t bDst = aDst + B_OFF;

    // ldmatrix lane addressing
    int sub = lane >> 3, r7 = lane & 7;
    // A x4: m0 rows 0-7 col0, m1 rows 8-15 col0, m2 rows 0-7 col16, m3 rows 8-15 col16
    uint32_t aLdm = sb + (uint32_t)(wm * 64 + (sub & 1) * 8 + r7) * PITCH
                       + (uint32_t)((sub >> 1) * 16);
    // B x2: m0 rows(n) col0, m1 same rows col16 (lanes 0-15; 16-31 mirrored/ignored)
    uint32_t bLdm = sb + B_OFF + (uint32_t)(wn * 8 + r7) * PITCH
                       + (uint32_t)(((lane >> 3) & 1) * 16);

    // valid j groups for this warp (n-tile trim; 600 = 8*75, no straddle)
    int nbase_w = n0 + wn * 8;
    int vj0 = nbase_w            < HH;
    int vj1 = nbase_w + 32       < HH;
    int vj2 = nbase_w + 64       < HH;
    int vj3 = nbase_w + 96       < HH;

    float acc[4][4][4];
#pragma unroll
    for (int i = 0; i < 4; i++)
#pragma unroll
        for (int j = 0; j < 4; j++)
#pragma unroll
            for (int q = 0; q < 4; q++) acc[i][j][q] = 0.f;

    // prologue: issue chunks 0,1 into slots 0,1
#pragma unroll
    for (int pc = 0; pc < 2; pc++) {
        uint32_t so = (uint32_t)pc * STAGE_BYTES;
#pragma unroll
        for (int q = 0; q < 4; q++) {
            cp16(aDst + so + q * 16, aSrc + pc * 128 + q * 16);
            cp16(bDst + so + q * 16, bSrc + pc * 128 + q * 16);
        }
        asm volatile("cp.async.commit_group;" ::: "memory");
    }

    // main loop
    for (int c = 0; c < NCHUNK; c++) {
        asm volatile("cp.async.wait_group 1;" ::: "memory");
        __syncthreads();
        int cn = c + 2;
        if (cn < NCHUNK) {
            uint32_t so = (uint32_t)(cn % 3) * STAGE_BYTES;
#pragma unroll
            for (int q = 0; q < 4; q++) {
                cp16(aDst + so + q * 16, aSrc + cn * 128 + q * 16);
                cp16(bDst + so + q * 16, bSrc + cn * 128 + q * 16);
            }
        }
        asm volatile("cp.async.commit_group;" ::: "memory");

        uint32_t stageOff = (uint32_t)(c % 3) * STAGE_BYTES;
#pragma unroll
        for (int ks = 0; ks < 4; ks++) {
            uint32_t afr[4][4], bfr[4][2];
            uint32_t aO = aLdm + stageOff + (uint32_t)ks * 32;
            uint32_t bO = bLdm + stageOff + (uint32_t)ks * 32;
            if (vj0) ldm_x2(bfr[0], bO);
            if (vj1) ldm_x2(bfr[1], bO + 32 * PITCH);
            if (vj2) ldm_x2(bfr[2], bO + 64 * PITCH);
            if (vj3) ldm_x2(bfr[3], bO + 96 * PITCH);
#pragma unroll
            for (int i = 0; i < 4; i++)
                ldm_x4(afr[i], aO + (uint32_t)i * (16 * PITCH));
#pragma unroll
            for (int i = 0; i < 4; i++) {
                if (vj0) mma16816(acc[i][0], afr[i], bfr[0]);
                if (vj1) mma16816(acc[i][1], afr[i], bfr[1]);
                if (vj2) mma16816(acc[i][2], afr[i], bfr[2]);
                if (vj3) mma16816(acc[i][3], afr[i], bfr[3]);
            }
        }
    }
    __syncthreads();  // smem reads done; reuse dsm for reduction

    // ---- epilogue: acc + Pt + Pe, relu, @W1 -> per-row partials
    float* red = (float*)dsm;  // [128][4][2]
    float pr[4][2][2];
#pragma unroll
    for (int i = 0; i < 4; i++)
#pragma unroll
        for (int hh = 0; hh < 2; hh++) { pr[i][hh][0] = 0.f; pr[i][hh][1] = 0.f; }

    const float* ptRow = Pt + (size_t)(b * TT + 2 * mt + wm) * NPAD;
    const float* peBase = Pe + (size_t)(b * EE) * NPAD;

#pragma unroll
    for (int j = 0; j < 4; j++) {
        int hcol = n0 + j * 32 + wn * 8 + t2;   // strided-j column mapping
#pragma unroll
        for (int cp = 0; cp < 2; cp++) {
            int h = hcol + cp;
            if (h < HH) {
                float pt = ptRow[h];
                float w10 = W1[2 * h], w11 = W1[2 * h + 1];
#pragma unroll
                for (int i = 0; i < 4; i++) {
                    float pe0 = peBase[(size_t)(i * 16 + g) * NPAD + h];
                    float pe1 = peBase[(size_t)(i * 16 + g + 8) * NPAD + h];
                    float v0 = fmaxf(acc[i][j][cp] + pt + pe0, 0.f);
                    float v1 = fmaxf(acc[i][j][2 + cp] + pt + pe1, 0.f);
                    pr[i][0][0] = fmaf(v0, w10, pr[i][0][0]);
                    pr[i][0][1] = fmaf(v0, w11, pr[i][0][1]);
                    pr[i][1][0] = fmaf(v1, w10, pr[i][1][0]);
                    pr[i][1][1] = fmaf(v1, w11, pr[i][1][1]);
                }
            }
        }
    }
#pragma unroll
    for (int i = 0; i < 4; i++)
#pragma unroll
        for (int hh = 0; hh < 2; hh++)
#pragma unroll
            for (int o = 0; o < 2; o++) {
                float v = pr[i][hh][o];
                v += __shfl_xor_sync(0xffffffffu, v, 1);
                v += __shfl_xor_sync(0xffffffffu, v, 2);
                pr[i][hh][o] = v;
            }
    if ((lane & 3) == 0) {
#pragma unroll
        for (int i = 0; i < 4; i++)
#pragma unroll
            for (int hh = 0; hh < 2; hh++) {
                int row = wm * 64 + i * 16 + g + hh * 8;
                red[(row * 4 + wn) * 2 + 0] = pr[i][hh][0];
                red[(row * 4 + wn) * 2 + 1] = pr[i][hh][1];
            }
    }
    __syncthreads();
    if (tid < 128) {
        int row = tid;
        float a0 = 0.f, a1 = 0.f;
#pragma unroll
        for (int wc = 0; wc < 4; wc++) {
            a0 += red[(row * 4 + wc) * 2 + 0];
            a1 += red[(row * 4 + wc) * 2 + 1];
        }
        int pair = (2 * mt + (row >> 6)) * EE + (row & 63);
        size_t oidx = ((size_t)nt * BB * NPAIR + (size_t)b * NPAIR + pair) * 2;
        part[oidx]     = a0;
        part[oidx + 1] = a1;
    }
}

// ---------------- kernel 5: reduce 5 partials + b1 ---------------------------
__global__ void reduce_out_kernel(const float* __restrict__ part,
                                  const float* __restrict__ b1,
                                  float* __restrict__ out) {
    int i = blockIdx.x * blockDim.x + threadIdx.x;
    float a = b1[i & 1];
#pragma unroll
    for (int t = 0; t < NTILES; t++)
        a += part[(size_t)t * BB * NPAIR * 2 + i];
    out[i] = a;
}

// ---------------- launch -----------------------------------------------------
extern "C" void kernel_launch(void* const* d_in, const int* in_sizes, int n_in,
                              void* d_out, int out_size) {
    const float* piece = (const float*)d_in[0];
    const int*   widx  = (const int*)d_in[1];
    const int*   tidx  = (const int*)d_in[2];
    const int*   eidx  = (const int*)d_in[3];
    const float* W0    = (const float*)d_in[4];
    const float* b0    = (const float*)d_in[5];
    const float* W1    = (const float*)d_in[6];
    const float* b1    = (const float*)d_in[7];
    float* out = (float*)d_out;

    float *wordp, *trigp, *entp, *ptp, *pep, *partp;
    __half *w0tp, *ap;
    cudaGetSymbolAddress((void**)&wordp, g_word);
    cudaGetSymbolAddress((void**)&trigp, g_trig);
    cudaGetSymbolAddress((void**)&entp,  g_ent);
    cudaGetSymbolAddress((void**)&w0tp,  g_W0T);
    cudaGetSymbolAddress((void**)&ap,    g_A);
    cudaGetSymbolAddress((void**)&ptp,   g_Pt);
    cudaGetSymbolAddress((void**)&pep,   g_Pe);
    cudaGetSymbolAddress((void**)&partp, g_part);

    cudaFuncSetAttribute(pair_mma_kernel,
                         cudaFuncAttributeMaxDynamicSharedMemorySize, SMEM_DYN);

    word_mean_kernel<<<dim3(WW, BB), 256>>>(piece, widx, wordp);
    spans_kernel<<<dim3(TT + EE, BB), 256>>>(wordp, tidx, eidx, trigp, entp);
    bprep_kernel<<<dim3(KF / 32, NPAD / 32), dim3(32, 32)>>>(W0, w0tp);
    agen_kernel<<<dim3(NPAIR, BB), 128>>>(trigp, entp, ap);
    pgemm_kernel<<<dim3(NTILES, 12), 256>>>(trigp, entp, w0tp, b0, ptp, pep);
    pair_mma_kernel<<<dim3(NTILES, 256), 256, SMEM_DYN>>>(
        ap, w0tp, ptp, pep, W1, partp);
    reduce_out_kernel<<<(BB * NPAIR * 2) / 1024, 1024>>>(partp, b1, out);
    (void)in_sizes; (void)n_in; (void)out_size;
}

// round 10
// speedup vs baseline: 1.0263x; 1.0263x over previous
#include <cuda_runtime.h>
#include <cuda_fp16.h>
#include <math.h>
#include <stdint.h>

// Problem constants
#define BB 16
#define PP 512
#define DD 1024
#define WW 400
#define TT 32
#define EE 64
#define HH 600
#define NPAIR (TT * EE)     // 2048
#define KF 4096             // W0T row length
#define KPOFF 2048          // pair-GEMM feature base: [t*e | |t-e|]
#define KP 2048             // pair-GEMM K
#define NPAD 640
#define KC 64               // k per chunk
#define NCHUNK 32           // KP / KC
#define NTILES 5            // h tiles of 128

// smem geometry (bytes): stage = A[128][64h] + B[128][64h], pitch 144
#define PITCH 144
#define B_OFF (128 * PITCH)               // 18432
#define STAGE_BYTES (2 * 128 * PITCH)     // 36864
#define NSTAGE 3
#define SMEM_DYN (NSTAGE * STAGE_BYTES)   // 110592
#define PGEMM_SMEM (2 * STAGE_BYTES)      // 73728

// ---------------- scratch ----------------------------------------------------
__device__ float g_word[(size_t)BB * WW * DD];
__device__ float g_trig[(size_t)BB * TT * DD];
__device__ float g_ent [(size_t)BB * EE * DD];
__device__ __half g_W0T[(size_t)NPAD * KF];            // W0^T fp16 [n][k]
__device__ __half g_A  [(size_t)BB * NPAIR * KP];      // pair features fp16 (134MB)
__device__ float g_Pt [(size_t)BB * TT * NPAD];
__device__ float g_Pe [(size_t)BB * EE * NPAD];
__device__ float g_part[(size_t)NTILES * BB * NPAIR * 2];

// ---------------- helpers ----------------------------------------------------
__device__ __forceinline__ void mma16816(float* c, const uint32_t* a, const uint32_t* b) {
    asm volatile(
        "mma.sync.aligned.m16n8k16.row.col.f32.f16.f16.f32 "
        "{%0,%1,%2,%3}, {%4,%5,%6,%7}, {%8,%9}, {%0,%1,%2,%3};"
        : "+f"(c[0]), "+f"(c[1]), "+f"(c[2]), "+f"(c[3])
        : "r"(a[0]), "r"(a[1]), "r"(a[2]), "r"(a[3]), "r"(b[0]), "r"(b[1]));
}
__device__ __forceinline__ void ldm_x4(uint32_t* r, uint32_t addr) {
    asm volatile("ldmatrix.sync.aligned.m8n8.x4.shared.b16 {%0,%1,%2,%3}, [%4];"
                 : "=r"(r[0]), "=r"(r[1]), "=r"(r[2]), "=r"(r[3]) : "r"(addr));
}
__device__ __forceinline__ void ldm_x2(uint32_t* r, uint32_t addr) {
    asm volatile("ldmatrix.sync.aligned.m8n8.x2.shared.b16 {%0,%1}, [%2];"
                 : "=r"(r[0]), "=r"(r[1]) : "r"(addr));
}
__device__ __forceinline__ void cp16(uint32_t dst, const void* src) {
    asm volatile("cp.async.ca.shared.global [%0], [%1], 16;" :: "r"(dst), "l"(src) : "memory");
}
__device__ __forceinline__ uint32_t smem_u32(const void* p) {
    uint32_t a;
    asm("{ .reg .u64 t; cvta.to.shared.u64 t, %1; cvt.u32.u64 %0, t; }"
        : "=r"(a) : "l"(p));
    return a;
}
__device__ __forceinline__ uint32_t pack_h2(float lo, float hi) {
    uint32_t r;
    asm("cvt.rn.f16x2.f32 %0, %1, %2;" : "=r"(r) : "f"(hi), "f"(lo));
    return r;
}

// ---------------- kernel 1: wordpiece -> word mean ---------------------------
__global__ void word_mean_kernel(const float* __restrict__ piece,
                                 const int* __restrict__ widx,
                                 float* __restrict__ out) {
    int w = blockIdx.x, b = blockIdx.y;
    int s = widx[(b * WW + w) * 2];
    int e = widx[(b * WW + w) * 2 + 1];
    float inv = 1.0f / (float)(e - s);
    const float* base = piece + (size_t)b * PP * DD;
    int t = threadIdx.x;
    float a0 = 0.f, a1 = 0.f, a2 = 0.f, a3 = 0.f;
    for (int r = s; r < e; r++) {
        float4 v = ((const float4*)(base + (size_t)r * DD))[t];
        a0 += v.x; a1 += v.y; a2 += v.z; a3 += v.w;
    }
    float4 o = make_float4(a0 * inv, a1 * inv, a2 * inv, a3 * inv);
    ((float4*)(out + (size_t)(b * WW + w) * DD))[t] = o;
}

// ---------------- kernel 2: fused span means + W0 transpose-to-fp16 ----------
// grid: (TT+EE)*BB span blocks, then 2560 bprep blocks. block 256.
#define NSPAN ((TT + EE) * BB)   // 1536
__global__ void spans_bprep_kernel(const float* __restrict__ words,
                                   const int* __restrict__ tidx,
                                   const int* __restrict__ eidx,
                                   const float* __restrict__ W0,
                                   float* __restrict__ trig,
                                   float* __restrict__ ent,
                                   __half* __restrict__ W0T) {
    __shared__ float tile[32][33];
    int bid = blockIdx.x;
    if (bid < NSPAN) {
        int m = bid % (TT + EE), b = bid / (TT + EE);
        const int* idx;
        float* out;
        int mm, M;
        if (m < TT) { idx = tidx; out = trig; mm = m; M = TT; }
        else        { idx = eidx; out = ent;  mm = m - TT; M = EE; }
        int s = idx[(b * M + mm) * 2];
        int e = idx[(b * M + mm) * 2 + 1];
        float inv = 1.0f / (float)(e - s);
        const float* base = words + (size_t)b * WW * DD;
        int t = threadIdx.x;
        float a0 = 0.f, a1 = 0.f, a2 = 0.f, a3 = 0.f;
        for (int r = s; r < e; r++) {
            float4 v = ((const float4*)(base + (size_t)r * DD))[t];
            a0 += v.x; a1 += v.y; a2 += v.z; a3 += v.w;
        }
        float4 o = make_float4(a0 * inv, a1 * inv, a2 * inv, a3 * inv);
        ((float4*)(out + (size_t)(b * M + mm) * DD))[t] = o;
    } else {
        int b2 = bid - NSPAN;               // 0..2559
        int k0 = (b2 & 127) * 32;           // KF/32 = 128
        int n0 = (b2 >> 7) * 32;            // NPAD/32 = 20
        int x = threadIdx.x & 31, y8 = threadIdx.x >> 5;  // 8 rows per pass
#pragma unroll
        for (int i = 0; i < 4; i++) {
            int y = y8 + i * 8;
            float v = 0.f;
            if (n0 + x < HH) v = W0[(size_t)(k0 + y) * HH + (n0 + x)];
            tile[y][x] = v;
        }
        __syncthreads();
#pragma unroll
        for (int i = 0; i < 4; i++) {
            int y = y8 + i * 8;
            W0T[(size_t)(n0 + y) * KF + (k0 + x)] = __float2half_rn(tile[x][y]);
        }
    }
}

// ---------------- kernel 3c: A-gen: pair features fp16 (2 pairs/block) -------
__global__ void agen_kernel(const float* __restrict__ trig,
                            const float* __restrict__ ent,
                            __half* __restrict__ A) {
    int pair = blockIdx.x * 2 + (threadIdx.x >> 7);
    int b = blockIdx.y;
    int t = pair >> 6, e = pair & 63;
    int tid = threadIdx.x & 127;
    const float4* tr = (const float4*)(trig + ((size_t)b * TT + t) * DD + tid * 8);
    const float4* er = (const float4*)(ent  + ((size_t)b * EE + e) * DD + tid * 8);
    float4 t0 = tr[0], t1 = tr[1];
    float4 e0 = er[0], e1 = er[1];
    size_t rowo = ((size_t)b * NPAIR + pair) * KP;
    uint4 p;
    p.x = pack_h2(t0.x * e0.x, t0.y * e0.y);
    p.y = pack_h2(t0.z * e0.z, t0.w * e0.w);
    p.z = pack_h2(t1.x * e1.x, t1.y * e1.y);
    p.w = pack_h2(t1.z * e1.z, t1.w * e1.w);
    *(uint4*)(A + rowo + tid * 8) = p;
    uint4 d;
    d.x = pack_h2(fabsf(t0.x - e0.x), fabsf(t0.y - e0.y));
    d.y = pack_h2(fabsf(t0.z - e0.z), fabsf(t0.w - e0.w));
    d.z = pack_h2(fabsf(t1.x - e1.x), fabsf(t1.y - e1.y));
    d.w = pack_h2(fabsf(t1.z - e1.z), fabsf(t1.w - e1.w));
    *(uint4*)(A + rowo + 1024 + tid * 8) = d;
}

// ---------------- kernel 3b: combined P GEMM, double-buffered ----------------
// grid (NTILES, 12): mtg<4 -> Pt rows (trig, +b0); else Pe rows.
__global__ __launch_bounds__(256)
void pgemm_kernel(const float* __restrict__ trig,
                  const float* __restrict__ ent,
                  const __half* __restrict__ W0T,
                  const float* __restrict__ b0,
                  float* __restrict__ Pt,
                  float* __restrict__ Pe) {
    extern __shared__ char pdsm[];
    uint32_t sb = smem_u32(pdsm);
    int tid = threadIdx.x;
    int lane = tid & 31, warp = tid >> 5;
    int wm = warp >> 2, wn = warp & 3;
    int g = lane >> 2, t2 = (lane & 3) * 2;
    int nt = blockIdx.x, mtg = blockIdx.y;
    int n0 = nt * 128;

    const float* X;
    float* C;
    const float* bias;
    int m0, koff;
    if (mtg < 4) { X = trig; C = Pt; bias = b0;      m0 = mtg * 128;       koff = 0;  }
    else         { X = ent;  C = Pe; bias = nullptr; m0 = (mtg - 4) * 128; koff = DD; }

    int prow = tid >> 1;
    int cb = (tid & 1) * 32;
    const float* xrow = X + (size_t)(m0 + prow) * DD;
    uint32_t aDst = sb + (uint32_t)prow * PITCH + cb * 2;
    uint32_t bDst = sb + B_OFF + (uint32_t)prow * PITCH + cb * 2;
    const __half* bSrcBase = W0T + (size_t)(n0 + prow) * KF + koff + cb;

    uint32_t aLd = sb + (uint32_t)(wm * 64 + g) * PITCH + (uint32_t)t2 * 2;
    uint32_t bLd = sb + B_OFF + (uint32_t)(wn * 32 + g) * PITCH + (uint32_t)t2 * 2;

    float acc[4][4][4];
#pragma unroll
    for (int i = 0; i < 4; i++)
#pragma unroll
        for (int j = 0; j < 4; j++)
#pragma unroll
            for (int q = 0; q < 4; q++) acc[i][j][q] = 0.f;

    // prologue: regs for chunk 0 + B cp chunk 0 -> slot 0
    float xv[32];
#pragma unroll
    for (int q = 0; q < 8; q++) {
        float4 v = ((const float4*)(xrow + cb))[q];
        xv[q*4+0] = v.x; xv[q*4+1] = v.y; xv[q*4+2] = v.z; xv[q*4+3] = v.w;
    }
    {
        const char* bs = (const char*)bSrcBase;
#pragma unroll
        for (int q = 0; q < 4; q++)
            cp16(bDst + q * 16, bs + q * 16);
        asm volatile("cp.async.commit_group;" ::: "memory");
    }

    for (int c = 0; c < DD / KC; c++) {
        uint32_t so = (uint32_t)(c & 1) * STAGE_BYTES;
        // store A chunk c from regs
#pragma unroll
        for (int gq = 0; gq < 4; gq++) {
            uint32_t p0 = pack_h2(xv[gq*8+0], xv[gq*8+1]);
            uint32_t p1 = pack_h2(xv[gq*8+2], xv[gq*8+3]);
            uint32_t p2 = pack_h2(xv[gq*8+4], xv[gq*8+5]);
            uint32_t p3 = pack_h2(xv[gq*8+6], xv[gq*8+7]);
            asm volatile("st.shared.v4.b32 [%0], {%1,%2,%3,%4};"
                         :: "r"(aDst + so + gq * 16), "r"(p0), "r"(p1), "r"(p2), "r"(p3) : "memory");
        }
        // prefetch chunk c+1 (regs + B cp into other slot)
        if (c < DD / KC - 1) {
#pragma unroll
            for (int q = 0; q < 8; q++) {
                float4 v = ((const float4*)(xrow + (c + 1) * KC + cb))[q];
                xv[q*4+0] = v.x; xv[q*4+1] = v.y; xv[q*4+2] = v.z; xv[q*4+3] = v.w;
            }
            uint32_t son = (uint32_t)((c + 1) & 1) * STAGE_BYTES;
            const char* bs = (const char*)(bSrcBase + (c + 1) * KC);
#pragma unroll
            for (int q = 0; q < 4; q++)
                cp16(bDst + son + q * 16, bs + q * 16);
            asm volatile("cp.async.commit_group;" ::: "memory");
            asm volatile("cp.async.wait_group 1;" ::: "memory");
        } else {
            asm volatile("cp.async.wait_group 0;" ::: "memory");
        }
        __syncthreads();
#pragma unroll
        for (int ks = 0; ks < 4; ks++) {
            uint32_t afr[4][4], bfr[4][2];
            uint32_t aO = aLd + so + (uint32_t)ks * 32;
            uint32_t bO = bLd + so + (uint32_t)ks * 32;
#pragma unroll
            for (int j = 0; j < 4; j++) {
                uint32_t o = bO + (uint32_t)j * (8 * PITCH);
                asm volatile("ld.shared.b32 %0, [%1];" : "=r"(bfr[j][0]) : "r"(o));
                asm volatile("ld.shared.b32 %0, [%1];" : "=r"(bfr[j][1]) : "r"(o + 16));
            }
#pragma unroll
            for (int i = 0; i < 4; i++) {
                uint32_t o = aO + (uint32_t)i * (16 * PITCH);
                asm volatile("ld.shared.b32 %0, [%1];" : "=r"(afr[i][0]) : "r"(o));
                asm volatile("ld.shared.b32 %0, [%1];" : "=r"(afr[i][1]) : "r"(o + 8 * PITCH));
                asm volatile("ld.shared.b32 %0, [%1];" : "=r"(afr[i][2]) : "r"(o + 16));
                asm volatile("ld.shared.b32 %0, [%1];" : "=r"(afr[i][3]) : "r"(o + 8 * PITCH + 16));
            }
#pragma unroll
            for (int i = 0; i < 4; i++)
#pragma unroll
                for (int j = 0; j < 4; j++)
                    mma16816(acc[i][j], afr[i], bfr[j]);
        }
        __syncthreads();
    }

#pragma unroll
    for (int j = 0; j < 4; j++) {
        int hcol = n0 + wn * 32 + j * 8 + t2;
#pragma unroll
        for (int cp = 0; cp < 2; cp++) {
            int h = hcol + cp;
            float bb = (bias && h < HH) ? bias[h] : 0.f;
#pragma unroll
            for (int i = 0; i < 4; i++) {
                int r0 = m0 + wm * 64 + i * 16 + g;
                C[(size_t)r0 * NPAD + h]       = acc[i][j][cp] + bb;
                C[(size_t)(r0 + 8) * NPAD + h] = acc[i][j][2 + cp] + bb;
            }
        }
    }
}

// ---------------- kernel 4: pair GEMM (ldmatrix, 3-stage cp.async) -----------
__global__ __launch_bounds__(256, 2)
void pair_mma_kernel(const __half* __restrict__ A,
                     const __half* __restrict__ W0T,
                     const float* __restrict__ Pt,
                     const float* __restrict__ Pe,
                     const float* __restrict__ W1,
                     float* __restrict__ part) {
    extern __shared__ char dsm[];
    uint32_t sb = smem_u32(dsm);
    int tid = threadIdx.x;
    int lane = tid & 31, warp = tid >> 5;
    int wm = warp >> 2, wn = warp & 3;
    int g = lane >> 2, t2 = (lane & 3) * 2;
    int nt = blockIdx.x, mtb = blockIdx.y;
    int b = mtb >> 4, mt = mtb & 15;
    int n0 = nt * 128;

    int prow = tid >> 1, pseg = tid & 1;
    const char* aSrc = (const char*)A + ((size_t)mtb * 128 + prow) * (KP * 2) + pseg * 64;
    const char* bSrc = (const char*)W0T + ((size_t)(n0 + prow) * KF + KPOFF) * 2 + pseg * 64;
    uint32_t aDst = sb + (uint32_t)prow * PITCH + pseg * 64;
    uint32_t bDst = aDst + B_OFF;

    int sub = lane >> 3, r7 = lane & 7;
    uint32_t aLdm = sb + (uint32_t)(wm * 64 + (sub & 1) * 8 + r7) * PITCH
                       + (uint32_t)((sub >> 1) * 16);
    uint32_t bLdm = sb + B_OFF + (uint32_t)(wn * 8 + r7) * PITCH
                       + (uint32_t)(((lane >> 3) & 1) * 16);

    int nbase_w = n0 + wn * 8;
    int vj0 = nbase_w            < HH;
    int vj1 = nbase_w + 32       < HH;
    int vj2 = nbase_w + 64       < HH;
    int vj3 = nbase_w + 96       < HH;

    float acc[4][4][4];
#pragma unroll
    for (int i = 0; i < 4; i++)
#pragma unroll
        for (int j = 0; j < 4; j++)
#pragma unroll
            for (int q = 0; q < 4; q++) acc[i][j][q] = 0.f;

#pragma unroll
    for (int pc = 0; pc < 2; pc++) {
        uint32_t so = (uint32_t)pc * STAGE_BYTES;
#pragma unroll
        for (int q = 0; q < 4; q++) {
            cp16(aDst + so + q * 16, aSrc + pc * 128 + q * 16);
            cp16(bDst + so + q * 16, bSrc + pc * 128 + q * 16);
        }
        asm volatile("cp.async.commit_group;" ::: "memory");
    }

    for (int c = 0; c < NCHUNK; c++) {
        asm volatile("cp.async.wait_group 1;" ::: "memory");
        __syncthreads();
        int cn = c + 2;
        if (cn < NCHUNK) {
            uint32_t so = (uint32_t)(cn % 3) * STAGE_BYTES;
#pragma unroll
            for (int q = 0; q < 4; q++) {
                cp16(aDst + so + q * 16, aSrc + cn * 128 + q * 16);
                cp16(bDst + so + q * 16, bSrc + cn * 128 + q * 16);
            }
        }
        asm volatile("cp.async.commit_group;" ::: "memory");

        uint32_t stageOff = (uint32_t)(c % 3) * STAGE_BYTES;
#pragma unroll
        for (int ks = 0; ks < 4; ks++) {
            uint32_t afr[4][4], bfr[4][2];
            uint32_t aO = aLdm + stageOff + (uint32_t)ks * 32;
            uint32_t bO = bLdm + stageOff + (uint32_t)ks * 32;
            if (vj0) ldm_x2(bfr[0], bO);
            if (vj1) ldm_x2(bfr[1], bO + 32 * PITCH);
            if (vj2) ldm_x2(bfr[2], bO + 64 * PITCH);
            if (vj3) ldm_x2(bfr[3], bO + 96 * PITCH);
#pragma unroll
            for (int i = 0; i < 4; i++)
                ldm_x4(afr[i], aO + (uint32_t)i * (16 * PITCH));
#pragma unroll
            for (int i = 0; i < 4; i++) {
                if (vj0) mma16816(acc[i][0], afr[i], bfr[0]);
                if (vj1) mma16816(acc[i][1], afr[i], bfr[1]);
                if (vj2) mma16816(acc[i][2], afr[i], bfr[2]);
                if (vj3) mma16816(acc[i][3], afr[i], bfr[3]);
            }
        }
    }
    __syncthreads();

    float* red = (float*)dsm;
    float pr[4][2][2];
#pragma unroll
    for (int i = 0; i < 4; i++)
#pragma unroll
        for (int hh = 0; hh < 2; hh++) { pr[i][hh][0] = 0.f; pr[i][hh][1] = 0.f; }

    const float* ptRow = Pt + (size_t)(b * TT + 2 * mt + wm) * NPAD;
    const float* peBase = Pe + (size_t)(b * EE) * NPAD;

#pragma unroll
    for (int j = 0; j < 4; j++) {
        int hcol = n0 + j * 32 + wn * 8 + t2;
#pragma unroll
        for (int cp = 0; cp < 2; cp++) {
            int h = hcol + cp;
            if (h < HH) {
                float pt = ptRow[h];
                float w10 = W1[2 * h], w11 = W1[2 * h + 1];
#pragma unroll
                for (int i = 0; i < 4; i++) {
                    float pe0 = peBase[(size_t)(i * 16 + g) * NPAD + h];
                    float pe1 = peBase[(size_t)(i * 16 + g + 8) * NPAD + h];
                    float v0 = fmaxf(acc[i][j][cp] + pt + pe0, 0.f);
                    float v1 = fmaxf(acc[i][j][2 + cp] + pt + pe1, 0.f);
                    pr[i][0][0] = fmaf(v0, w10, pr[i][0][0]);
                    pr[i][0][1] = fmaf(v0, w11, pr[i][0][1]);
                    pr[i][1][0] = fmaf(v1, w10, pr[i][1][0]);
                    pr[i][1][1] = fmaf(v1, w11, pr[i][1][1]);
                }
            }
        }
    }
#pragma unroll
    for (int i = 0; i < 4; i++)
#pragma unroll
        for (int hh = 0; hh < 2; hh++)
#pragma unroll
            for (int o = 0; o < 2; o++) {
                float v = pr[i][hh][o];
                v += __shfl_xor_sync(0xffffffffu, v, 1);
                v += __shfl_xor_sync(0xffffffffu, v, 2);
                pr[i][hh][o] = v;
            }
    if ((lane & 3) == 0) {
#pragma unroll
        for (int i = 0; i < 4; i++)
#pragma unroll
            for (int hh = 0; hh < 2; hh++) {
                int row = wm * 64 + i * 16 + g + hh * 8;
                red[(row * 4 + wn) * 2 + 0] = pr[i][hh][0];
                red[(row * 4 + wn) * 2 + 1] = pr[i][hh][1];
            }
    }
    __syncthreads();
    if (tid < 128) {
        int row = tid;
        float a0 = 0.f, a1 = 0.f;
#pragma unroll
        for (int wc = 0; wc < 4; wc++) {
            a0 += red[(row * 4 + wc) * 2 + 0];
            a1 += red[(row * 4 + wc) * 2 + 1];
        }
        int pair = (2 * mt + (row >> 6)) * EE + (row & 63);
        size_t oidx = ((size_t)nt * BB * NPAIR + (size_t)b * NPAIR + pair) * 2;
        part[oidx]     = a0;
        part[oidx + 1] = a1;
    }
}

// ---------------- kernel 5: reduce 5 partials + b1 ---------------------------
__global__ void reduce_out_kernel(const float* __restrict__ part,
                                  const float* __restrict__ b1,
                                  float* __restrict__ out) {
    int i = blockIdx.x * blockDim.x + threadIdx.x;
    float a = b1[i & 1];
#pragma unroll
    for (int t = 0; t < NTILES; t++)
        a += part[(size_t)t * BB * NPAIR * 2 + i];
    out[i] = a;
}

// ---------------- launch -----------------------------------------------------
extern "C" void kernel_launch(void* const* d_in, const int* in_sizes, int n_in,
                              void* d_out, int out_size) {
    const float* piece = (const float*)d_in[0];
    const int*   widx  = (const int*)d_in[1];
    const int*   tidx  = (const int*)d_in[2];
    const int*   eidx  = (const int*)d_in[3];
    const float* W0    = (const float*)d_in[4];
    const float* b0    = (const float*)d_in[5];
    const float* W1    = (const float*)d_in[6];
    const float* b1    = (const float*)d_in[7];
    float* out = (float*)d_out;

    float *wordp, *trigp, *entp, *ptp, *pep, *partp;
    __half *w0tp, *ap;
    cudaGetSymbolAddress((void**)&wordp, g_word);
    cudaGetSymbolAddress((void**)&trigp, g_trig);
    cudaGetSymbolAddress((void**)&entp,  g_ent);
    cudaGetSymbolAddress((void**)&w0tp,  g_W0T);
    cudaGetSymbolAddress((void**)&ap,    g_A);
    cudaGetSymbolAddress((void**)&ptp,   g_Pt);
    cudaGetSymbolAddress((void**)&pep,   g_Pe);
    cudaGetSymbolAddress((void**)&partp, g_part);

    cudaFuncSetAttribute(pair_mma_kernel,
                         cudaFuncAttributeMaxDynamicSharedMemorySize, SMEM_DYN);
    cudaFuncSetAttribute(pgemm_kernel,
                         cudaFuncAttributeMaxDynamicSharedMemorySize, PGEMM_SMEM);

    word_mean_kernel<<<dim3(WW, BB), 256>>>(piece, widx, wordp);
    spans_bprep_kernel<<<NSPAN + (KF / 32) * (NPAD / 32), 256>>>(
        wordp, tidx, eidx, W0, trigp, entp, w0tp);
    agen_kernel<<<dim3(NPAIR / 2, BB), 256>>>(trigp, entp, ap);
    pgemm_kernel<<<dim3(NTILES, 12), 256, PGEMM_SMEM>>>(
        trigp, entp, w0tp, b0, ptp, pep);
    pair_mma_kernel<<<dim3(NTILES, 256), 256, SMEM_DYN>>>(
        ap, w0tp, ptp, pep, W1, partp);
    reduce_out_kernel<<<(BB * NPAIR * 2) / 1024, 1024>>>(partp, b1, out);
    (void)in_sizes; (void)n_in; (void)out_size;
}

// round 11
// speedup vs baseline: 1.0405x; 1.0138x over previous
#include <cuda_runtime.h>
#include <cuda_fp16.h>
#include <math.h>
#include <stdint.h>

// Problem constants
#define BB 16
#define PP 512
#define DD 1024
#define WW 400
#define TT 32
#define EE 64
#define HH 600
#define NPAIR (TT * EE)     // 2048
#define KF 4096             // W0T row length
#define KPOFF 2048          // pair-GEMM feature base: [t*e | |t-e|]
#define KP 2048             // pair-GEMM K
#define NPAD 640
#define KC 64               // k per chunk
#define NCHUNK 32           // KP / KC
#define NTILES 5            // h tiles of 128

// smem geometry (bytes): stage = A[128][64h] + B[128][64h], pitch 144
#define PITCH 144
#define B_OFF (128 * PITCH)               // 18432
#define STAGE_BYTES (2 * 128 * PITCH)     // 36864
#define NSTAGE 3
#define SMEM_DYN (NSTAGE * STAGE_BYTES)   // 110592
#define PGEMM_SMEM (2 * STAGE_BYTES)      // 73728
#define PGEMM_BLOCKS (NTILES * 12)        // 60

// ---------------- scratch ----------------------------------------------------
__device__ float g_word[(size_t)BB * WW * DD];
__device__ float g_trig[(size_t)BB * TT * DD];
__device__ float g_ent [(size_t)BB * EE * DD];
__device__ __half g_W0T[(size_t)NPAD * KF];            // W0^T fp16 [n][k]
__device__ __half g_A  [(size_t)BB * NPAIR * KP];      // pair features fp16 (134MB)
__device__ float g_Pt [(size_t)BB * TT * NPAD];
__device__ float g_Pe [(size_t)BB * EE * NPAD];
__device__ float g_part[(size_t)NTILES * BB * NPAIR * 2];

// ---------------- helpers ----------------------------------------------------
__device__ __forceinline__ void mma16816(float* c, const uint32_t* a, const uint32_t* b) {
    asm volatile(
        "mma.sync.aligned.m16n8k16.row.col.f32.f16.f16.f32 "
        "{%0,%1,%2,%3}, {%4,%5,%6,%7}, {%8,%9}, {%0,%1,%2,%3};"
        : "+f"(c[0]), "+f"(c[1]), "+f"(c[2]), "+f"(c[3])
        : "r"(a[0]), "r"(a[1]), "r"(a[2]), "r"(a[3]), "r"(b[0]), "r"(b[1]));
}
__device__ __forceinline__ void ldm_x4(uint32_t* r, uint32_t addr) {
    asm volatile("ldmatrix.sync.aligned.m8n8.x4.shared.b16 {%0,%1,%2,%3}, [%4];"
                 : "=r"(r[0]), "=r"(r[1]), "=r"(r[2]), "=r"(r[3]) : "r"(addr));
}
__device__ __forceinline__ void ldm_x2(uint32_t* r, uint32_t addr) {
    asm volatile("ldmatrix.sync.aligned.m8n8.x2.shared.b16 {%0,%1}, [%2];"
                 : "=r"(r[0]), "=r"(r[1]) : "r"(addr));
}
__device__ __forceinline__ void cp16(uint32_t dst, const void* src) {
    asm volatile("cp.async.ca.shared.global [%0], [%1], 16;" :: "r"(dst), "l"(src) : "memory");
}
__device__ __forceinline__ uint32_t smem_u32(const void* p) {
    uint32_t a;
    asm("{ .reg .u64 t; cvta.to.shared.u64 t, %1; cvt.u32.u64 %0, t; }"
        : "=r"(a) : "l"(p));
    return a;
}
__device__ __forceinline__ uint32_t pack_h2(float lo, float hi) {
    uint32_t r;
    asm("cvt.rn.f16x2.f32 %0, %1, %2;" : "=r"(r) : "f"(hi), "f"(lo));
    return r;
}

// ---------------- kernel 1: wordpiece -> word mean ---------------------------
__global__ void word_mean_kernel(const float* __restrict__ piece,
                                 const int* __restrict__ widx,
                                 float* __restrict__ out) {
    int w = blockIdx.x, b = blockIdx.y;
    int s = widx[(b * WW + w) * 2];
    int e = widx[(b * WW + w) * 2 + 1];
    float inv = 1.0f / (float)(e - s);
    const float* base = piece + (size_t)b * PP * DD;
    int t = threadIdx.x;
    float a0 = 0.f, a1 = 0.f, a2 = 0.f, a3 = 0.f;
    for (int r = s; r < e; r++) {
        float4 v = ((const float4*)(base + (size_t)r * DD))[t];
        a0 += v.x; a1 += v.y; a2 += v.z; a3 += v.w;
    }
    float4 o = make_float4(a0 * inv, a1 * inv, a2 * inv, a3 * inv);
    ((float4*)(out + (size_t)(b * WW + w) * DD))[t] = o;
}

// ---------------- kernel 2: fused span means + W0 transpose-to-fp16 ----------
#define NSPAN ((TT + EE) * BB)   // 1536
__global__ void spans_bprep_kernel(const float* __restrict__ words,
                                   const int* __restrict__ tidx,
                                   const int* __restrict__ eidx,
                                   const float* __restrict__ W0,
                                   float* __restrict__ trig,
                                   float* __restrict__ ent,
                                   __half* __restrict__ W0T) {
    __shared__ float tile[32][33];
    int bid = blockIdx.x;
    if (bid < NSPAN) {
        int m = bid % (TT + EE), b = bid / (TT + EE);
        const int* idx;
        float* out;
        int mm, M;
        if (m < TT) { idx = tidx; out = trig; mm = m; M = TT; }
        else        { idx = eidx; out = ent;  mm = m - TT; M = EE; }
        int s = idx[(b * M + mm) * 2];
        int e = idx[(b * M + mm) * 2 + 1];
        float inv = 1.0f / (float)(e - s);
        const float* base = words + (size_t)b * WW * DD;
        int t = threadIdx.x;
        float a0 = 0.f, a1 = 0.f, a2 = 0.f, a3 = 0.f;
        for (int r = s; r < e; r++) {
            float4 v = ((const float4*)(base + (size_t)r * DD))[t];
            a0 += v.x; a1 += v.y; a2 += v.z; a3 += v.w;
        }
        float4 o = make_float4(a0 * inv, a1 * inv, a2 * inv, a3 * inv);
        ((float4*)(out + (size_t)(b * M + mm) * DD))[t] = o;
    } else {
        int b2 = bid - NSPAN;               // 0..2559
        int k0 = (b2 & 127) * 32;
        int n0 = (b2 >> 7) * 32;
        int x = threadIdx.x & 31, y8 = threadIdx.x >> 5;
#pragma unroll
        for (int i = 0; i < 4; i++) {
            int y = y8 + i * 8;
            float v = 0.f;
            if (n0 + x < HH) v = W0[(size_t)(k0 + y) * HH + (n0 + x)];
            tile[y][x] = v;
        }
        __syncthreads();
#pragma unroll
        for (int i = 0; i < 4; i++) {
            int y = y8 + i * 8;
            W0T[(size_t)(n0 + y) * KF + (k0 + x)] = __float2half_rn(tile[x][y]);
        }
    }
}

// ---------------- kernel 3: merged prep = pgemm (60 blocks) + agen (rest) ----
// blocks [0,60): P GEMM (Pt/Pe) at nt = bid%5, mtg = bid/5 (latency-bound,
//   scheduled first). blocks [60, 60+16384): A-gen, 2 pairs per block.
// Both independent (consume trig/ent only) -> co-resident on the chip.
__global__ __launch_bounds__(256)
void prep_kernel(const float* __restrict__ trig,
                 const float* __restrict__ ent,
                 const __half* __restrict__ W0T,
                 const float* __restrict__ b0,
                 float* __restrict__ Pt,
                 float* __restrict__ Pe,
                 __half* __restrict__ A) {
    extern __shared__ char pdsm[];
    int bid = blockIdx.x;
    int tid = threadIdx.x;

    if (bid >= PGEMM_BLOCKS) {
        // ---------------- agen path ----------------
        int bid2 = bid - PGEMM_BLOCKS;
        int b = bid2 >> 10;                    // / 1024
        int pair = (bid2 & 1023) * 2 + (tid >> 7);
        int t = pair >> 6, e = pair & 63;
        int lt = tid & 127;
        const float4* tr = (const float4*)(trig + ((size_t)b * TT + t) * DD + lt * 8);
        const float4* er = (const float4*)(ent  + ((size_t)b * EE + e) * DD + lt * 8);
        float4 t0 = tr[0], t1 = tr[1];
        float4 e0 = er[0], e1 = er[1];
        size_t rowo = ((size_t)b * NPAIR + pair) * KP;
        uint4 p;
        p.x = pack_h2(t0.x * e0.x, t0.y * e0.y);
        p.y = pack_h2(t0.z * e0.z, t0.w * e0.w);
        p.z = pack_h2(t1.x * e1.x, t1.y * e1.y);
        p.w = pack_h2(t1.z * e1.z, t1.w * e1.w);
        *(uint4*)(A + rowo + lt * 8) = p;
        uint4 d;
        d.x = pack_h2(fabsf(t0.x - e0.x), fabsf(t0.y - e0.y));
        d.y = pack_h2(fabsf(t0.z - e0.z), fabsf(t0.w - e0.w));
        d.z = pack_h2(fabsf(t1.x - e1.x), fabsf(t1.y - e1.y));
        d.w = pack_h2(fabsf(t1.z - e1.z), fabsf(t1.w - e1.w));
        *(uint4*)(A + rowo + 1024 + lt * 8) = d;
        return;
    }

    // ---------------- pgemm path (double-buffered) ----------------
    uint32_t sb = smem_u32(pdsm);
    int lane = tid & 31, warp = tid >> 5;
    int wm = warp >> 2, wn = warp & 3;
    int g = lane >> 2, t2 = (lane & 3) * 2;
    int nt = bid % NTILES, mtg = bid / NTILES;
    int n0 = nt * 128;

    const float* X;
    float* C;
    const float* bias;
    int m0, koff;
    if (mtg < 4) { X = trig; C = Pt; bias = b0;      m0 = mtg * 128;       koff = 0;  }
    else         { X = ent;  C = Pe; bias = nullptr; m0 = (mtg - 4) * 128; koff = DD; }

    int prow = tid >> 1;
    int cb = (tid & 1) * 32;
    const float* xrow = X + (size_t)(m0 + prow) * DD;
    uint32_t aDst = sb + (uint32_t)prow * PITCH + cb * 2;
    uint32_t bDst = sb + B_OFF + (uint32_t)prow * PITCH + cb * 2;
    const __half* bSrcBase = W0T + (size_t)(n0 + prow) * KF + koff + cb;

    uint32_t aLd = sb + (uint32_t)(wm * 64 + g) * PITCH + (uint32_t)t2 * 2;
    uint32_t bLd = sb + B_OFF + (uint32_t)(wn * 32 + g) * PITCH + (uint32_t)t2 * 2;

    float acc[4][4][4];
#pragma unroll
    for (int i = 0; i < 4; i++)
#pragma unroll
        for (int j = 0; j < 4; j++)
#pragma unroll
            for (int q = 0; q < 4; q++) acc[i][j][q] = 0.f;

    float xv[32];
#pragma unroll
    for (int q = 0; q < 8; q++) {
        float4 v = ((const float4*)(xrow + cb))[q];
        xv[q*4+0] = v.x; xv[q*4+1] = v.y; xv[q*4+2] = v.z; xv[q*4+3] = v.w;
    }
    {
        const char* bs = (const char*)bSrcBase;
#pragma unroll
        for (int q = 0; q < 4; q++)
            cp16(bDst + q * 16, bs + q * 16);
        asm volatile("cp.async.commit_group;" ::: "memory");
    }

    for (int c = 0; c < DD / KC; c++) {
        uint32_t so = (uint32_t)(c & 1) * STAGE_BYTES;
#pragma unroll
        for (int gq = 0; gq < 4; gq++) {
            uint32_t p0 = pack_h2(xv[gq*8+0], xv[gq*8+1]);
            uint32_t p1 = pack_h2(xv[gq*8+2], xv[gq*8+3]);
            uint32_t p2 = pack_h2(xv[gq*8+4], xv[gq*8+5]);
            uint32_t p3 = pack_h2(xv[gq*8+6], xv[gq*8+7]);
            asm volatile("st.shared.v4.b32 [%0], {%1,%2,%3,%4};"
                         :: "r"(aDst + so + gq * 16), "r"(p0), "r"(p1), "r"(p2), "r"(p3) : "memory");
        }
        if (c < DD / KC - 1) {
#pragma unroll
            for (int q = 0; q < 8; q++) {
                float4 v = ((const float4*)(xrow + (c + 1) * KC + cb))[q];
                xv[q*4+0] = v.x; xv[q*4+1] = v.y; xv[q*4+2] = v.z; xv[q*4+3] = v.w;
            }
            uint32_t son = (uint32_t)((c + 1) & 1) * STAGE_BYTES;
            const char* bs = (const char*)(bSrcBase + (c + 1) * KC);
#pragma unroll
            for (int q = 0; q < 4; q++)
                cp16(bDst + son + q * 16, bs + q * 16);
            asm volatile("cp.async.commit_group;" ::: "memory");
            asm volatile("cp.async.wait_group 1;" ::: "memory");
        } else {
            asm volatile("cp.async.wait_group 0;" ::: "memory");
        }
        __syncthreads();
#pragma unroll
        for (int ks = 0; ks < 4; ks++) {
            uint32_t afr[4][4], bfr[4][2];
            uint32_t aO = aLd + so + (uint32_t)ks * 32;
            uint32_t bO = bLd + so + (uint32_t)ks * 32;
#pragma unroll
            for (int j = 0; j < 4; j++) {
                uint32_t o = bO + (uint32_t)j * (8 * PITCH);
                asm volatile("ld.shared.b32 %0, [%1];" : "=r"(bfr[j][0]) : "r"(o));
                asm volatile("ld.shared.b32 %0, [%1];" : "=r"(bfr[j][1]) : "r"(o + 16));
            }
#pragma unroll
            for (int i = 0; i < 4; i++) {
                uint32_t o = aO + (uint32_t)i * (16 * PITCH);
                asm volatile("ld.shared.b32 %0, [%1];" : "=r"(afr[i][0]) : "r"(o));
                asm volatile("ld.shared.b32 %0, [%1];" : "=r"(afr[i][1]) : "r"(o + 8 * PITCH));
                asm volatile("ld.shared.b32 %0, [%1];" : "=r"(afr[i][2]) : "r"(o + 16));
                asm volatile("ld.shared.b32 %0, [%1];" : "=r"(afr[i][3]) : "r"(o + 8 * PITCH + 16));
            }
#pragma unroll
            for (int i = 0; i < 4; i++)
#pragma unroll
                for (int j = 0; j < 4; j++)
                    mma16816(acc[i][j], afr[i], bfr[j]);
        }
        __syncthreads();
    }

#pragma unroll
    for (int j = 0; j < 4; j++) {
        int hcol = n0 + wn * 32 + j * 8 + t2;
#pragma unroll
        for (int cp = 0; cp < 2; cp++) {
            int h = hcol + cp;
            float bb = (bias && h < HH) ? bias[h] : 0.f;
#pragma unroll
            for (int i = 0; i < 4; i++) {
                int r0 = m0 + wm * 64 + i * 16 + g;
                C[(size_t)r0 * NPAD + h]       = acc[i][j][cp] + bb;
                C[(size_t)(r0 + 8) * NPAD + h] = acc[i][j][2 + cp] + bb;
            }
        }
    }
}

// ---------------- kernel 4: pair GEMM (ldmatrix, 3-stage cp.async) -----------
__global__ __launch_bounds__(256, 2)
void pair_mma_kernel(const __half* __restrict__ A,
                     const __half* __restrict__ W0T,
                     const float* __restrict__ Pt,
                     const float* __restrict__ Pe,
                     const float* __restrict__ W1,
                     float* __restrict__ part) {
    extern __shared__ char dsm[];
    uint32_t sb = smem_u32(dsm);
    int tid = threadIdx.x;
    int lane = tid & 31, warp = tid >> 5;
    int wm = warp >> 2, wn = warp & 3;
    int g = lane >> 2, t2 = (lane & 3) * 2;
    int nt = blockIdx.x, mtb = blockIdx.y;
    int b = mtb >> 4, mt = mtb & 15;
    int n0 = nt * 128;

    int prow = tid >> 1, pseg = tid & 1;
    const char* aSrc = (const char*)A + ((size_t)mtb * 128 + prow) * (KP * 2) + pseg * 64;
    const char* bSrc = (const char*)W0T + ((size_t)(n0 + prow) * KF + KPOFF) * 2 + pseg * 64;
    uint32_t aDst = sb + (uint32_t)prow * PITCH + pseg * 64;
    uint32_t bDst = aDst + B_OFF;

    int sub = lane >> 3, r7 = lane & 7;
    uint32_t aLdm = sb + (uint32_t)(wm * 64 + (sub & 1) * 8 + r7) * PITCH
                       + (uint32_t)((sub >> 1) * 16);
    uint32_t bLdm = sb + B_OFF + (uint32_t)(wn * 8 + r7) * PITCH
                       + (uint32_t)(((lane >> 3) & 1) * 16);

    int nbase_w = n0 + wn * 8;
    int vj0 = nbase_w            < HH;
    int vj1 = nbase_w + 32       < HH;
    int vj2 = nbase_w + 64       < HH;
    int vj3 = nbase_w + 96       < HH;

    float acc[4][4][4];
#pragma unroll
    for (int i = 0; i < 4; i++)
#pragma unroll
        for (int j = 0; j < 4; j++)
#pragma unroll
            for (int q = 0; q < 4; q++) acc[i][j][q] = 0.f;

#pragma unroll
    for (int pc = 0; pc < 2; pc++) {
        uint32_t so = (uint32_t)pc * STAGE_BYTES;
#pragma unroll
        for (int q = 0; q < 4; q++) {
            cp16(aDst + so + q * 16, aSrc + pc * 128 + q * 16);
            cp16(bDst + so + q * 16, bSrc + pc * 128 + q * 16);
        }
        asm volatile("cp.async.commit_group;" ::: "memory");
    }

    for (int c = 0; c < NCHUNK; c++) {
        asm volatile("cp.async.wait_group 1;" ::: "memory");
        __syncthreads();
        int cn = c + 2;
        if (cn < NCHUNK) {
            uint32_t so = (uint32_t)(cn % 3) * STAGE_BYTES;
#pragma unroll
            for (int q = 0; q < 4; q++) {
                cp16(aDst + so + q * 16, aSrc + cn * 128 + q * 16);
                cp16(bDst + so + q * 16, bSrc + cn * 128 + q * 16);
            }
        }
        asm volatile("cp.async.commit_group;" ::: "memory");

        uint32_t stageOff = (uint32_t)(c % 3) * STAGE_BYTES;
#pragma unroll
        for (int ks = 0; ks < 4; ks++) {
            uint32_t afr[4][4], bfr[4][2];
            uint32_t aO = aLdm + stageOff + (uint32_t)ks * 32;
            uint32_t bO = bLdm + stageOff + (uint32_t)ks * 32;
            if (vj0) ldm_x2(bfr[0], bO);
            if (vj1) ldm_x2(bfr[1], bO + 32 * PITCH);
            if (vj2) ldm_x2(bfr[2], bO + 64 * PITCH);
            if (vj3) ldm_x2(bfr[3], bO + 96 * PITCH);
#pragma unroll
            for (int i = 0; i < 4; i++)
                ldm_x4(afr[i], aO + (uint32_t)i * (16 * PITCH));
#pragma unroll
            for (int i = 0; i < 4; i++) {
                if (vj0) mma16816(acc[i][0], afr[i], bfr[0]);
                if (vj1) mma16816(acc[i][1], afr[i], bfr[1]);
                if (vj2) mma16816(acc[i][2], afr[i], bfr[2]);
                if (vj3) mma16816(acc[i][3], afr[i], bfr[3]);
            }
        }
    }
    __syncthreads();

    float* red = (float*)dsm;
    float pr[4][2][2];
#pragma unroll
    for (int i = 0; i < 4; i++)
#pragma unroll
        for (int hh = 0; hh < 2; hh++) { pr[i][hh][0] = 0.f; pr[i][hh][1] = 0.f; }

    const float* ptRow = Pt + (size_t)(b * TT + 2 * mt + wm) * NPAD;
    const float* peBase = Pe + (size_t)(b * EE) * NPAD;

#pragma unroll
    for (int j = 0; j < 4; j++) {
        int hcol = n0 + j * 32 + wn * 8 + t2;
#pragma unroll
        for (int cp = 0; cp < 2; cp++) {
            int h = hcol + cp;
            if (h < HH) {
                float pt = ptRow[h];
                float w10 = W1[2 * h], w11 = W1[2 * h + 1];
#pragma unroll
                for (int i = 0; i < 4; i++) {
                    float pe0 = peBase[(size_t)(i * 16 + g) * NPAD + h];
                    float pe1 = peBase[(size_t)(i * 16 + g + 8) * NPAD + h];
                    float v0 = fmaxf(acc[i][j][cp] + pt + pe0, 0.f);
                    float v1 = fmaxf(acc[i][j][2 + cp] + pt + pe1, 0.f);
                    pr[i][0][0] = fmaf(v0, w10, pr[i][0][0]);
                    pr[i][0][1] = fmaf(v0, w11, pr[i][0][1]);
                    pr[i][1][0] = fmaf(v1, w10, pr[i][1][0]);
                    pr[i][1][1] = fmaf(v1, w11, pr[i][1][1]);
                }
            }
        }
    }
#pragma unroll
    for (int i = 0; i < 4; i++)
#pragma unroll
        for (int hh = 0; hh < 2; hh++)
#pragma unroll
            for (int o = 0; o < 2; o++) {
                float v = pr[i][hh][o];
                v += __shfl_xor_sync(0xffffffffu, v, 1);
                v += __shfl_xor_sync(0xffffffffu, v, 2);
                pr[i][hh][o] = v;
            }
    if ((lane & 3) == 0) {
#pragma unroll
        for (int i = 0; i < 4; i++)
#pragma unroll
            for (int hh = 0; hh < 2; hh++) {
                int row = wm * 64 + i * 16 + g + hh * 8;
                red[(row * 4 + wn) * 2 + 0] = pr[i][hh][0];
                red[(row * 4 + wn) * 2 + 1] = pr[i][hh][1];
            }
    }
    __syncthreads();
    if (tid < 128) {
        int row = tid;
        float a0 = 0.f, a1 = 0.f;
#pragma unroll
        for (int wc = 0; wc < 4; wc++) {
            a0 += red[(row * 4 + wc) * 2 + 0];
            a1 += red[(row * 4 + wc) * 2 + 1];
        }
        int pair = (2 * mt + (row >> 6)) * EE + (row & 63);
        size_t oidx = ((size_t)nt * BB * NPAIR + (size_t)b * NPAIR + pair) * 2;
        part[oidx]     = a0;
        part[oidx + 1] = a1;
    }
}

// ---------------- kernel 5: reduce 5 partials + b1 ---------------------------
__global__ void reduce_out_kernel(const float* __restrict__ part,
                                  const float* __restrict__ b1,
                                  float* __restrict__ out) {
    int i = blockIdx.x * blockDim.x + threadIdx.x;
    float a = b1[i & 1];
#pragma unroll
    for (int t = 0; t < NTILES; t++)
        a += part[(size_t)t * BB * NPAIR * 2 + i];
    out[i] = a;
}

// ---------------- launch -----------------------------------------------------
extern "C" void kernel_launch(void* const* d_in, const int* in_sizes, int n_in,
                              void* d_out, int out_size) {
    const float* piece = (const float*)d_in[0];
    const int*   widx  = (const int*)d_in[1];
    const int*   tidx  = (const int*)d_in[2];
    const int*   eidx  = (const int*)d_in[3];
    const float* W0    = (const float*)d_in[4];
    const float* b0    = (const float*)d_in[5];
    const float* W1    = (const float*)d_in[6];
    const float* b1    = (const float*)d_in[7];
    float* out = (float*)d_out;

    float *wordp, *trigp, *entp, *ptp, *pep, *partp;
    __half *w0tp, *ap;
    cudaGetSymbolAddress((void**)&wordp, g_word);
    cudaGetSymbolAddress((void**)&trigp, g_trig);
    cudaGetSymbolAddress((void**)&entp,  g_ent);
    cudaGetSymbolAddress((void**)&w0tp,  g_W0T);
    cudaGetSymbolAddress((void**)&ap,    g_A);
    cudaGetSymbolAddress((void**)&ptp,   g_Pt);
    cudaGetSymbolAddress((void**)&pep,   g_Pe);
    cudaGetSymbolAddress((void**)&partp, g_part);

    cudaFuncSetAttribute(pair_mma_kernel,
                         cudaFuncAttributeMaxDynamicSharedMemorySize, SMEM_DYN);
    cudaFuncSetAttribute(prep_kernel,
                         cudaFuncAttributeMaxDynamicSharedMemorySize, PGEMM_SMEM);

    word_mean_kernel<<<dim3(WW, BB), 256>>>(piece, widx, wordp);
    spans_bprep_kernel<<<NSPAN + (KF / 32) * (NPAD / 32), 256>>>(
        wordp, tidx, eidx, W0, trigp, entp, w0tp);
    prep_kernel<<<PGEMM_BLOCKS + (NPAIR / 2) * BB, 256, PGEMM_SMEM>>>(
        trigp, entp, w0tp, b0, ptp, pep, ap);
    pair_mma_kernel<<<dim3(NTILES, 256), 256, SMEM_DYN>>>(
        ap, w0tp, ptp, pep, W1, partp);
    reduce_out_kernel<<<(BB * NPAIR * 2) / 1024, 1024>>>(partp, b1, out);
    (void)in_sizes; (void)n_in; (void)out_size;
}

// round 13
// speedup vs baseline: 1.2327x; 1.1848x over previous
#include <cuda_runtime.h>
#include <cuda_fp16.h>
#include <math.h>
#include <stdint.h>

// Problem constants
#define BB 16
#define PP 512
#define DD 1024
#define WW 400
#define TT 32
#define EE 64
#define HH 600
#define NPAIR (TT * EE)     // 2048
#define KF 4096             // W0T row length
#define KPOFF 2048          // pair-GEMM feature base: [t*e | |t-e|]
#define KP 2048             // pair-GEMM K
#define NPAD 640
#define KC 64               // k per chunk
#define NCHUNK 32           // KP / KC
#define NTILES 5            // h tiles of 128

// smem geometry (bytes): stage = A[128][64h] + B[128][64h], pitch 144
#define PITCH 144
#define B_OFF (128 * PITCH)               // 18432
#define STAGE_BYTES (2 * 128 * PITCH)     // 36864
#define NSTAGE 3
#define SMEM_DYN (NSTAGE * STAGE_BYTES)   // 110592
#define PGEMM_SMEM (2 * STAGE_BYTES)      // 73728
#define PGEMM_BLOCKS (NTILES * 12)        // 60

// ---------------- scratch ----------------------------------------------------
__device__ float g_word[(size_t)BB * WW * DD];
__device__ float g_trig[(size_t)BB * TT * DD];
__device__ float g_ent [(size_t)BB * EE * DD];
__device__ __half g_W0T[(size_t)NPAD * KF];            // W0^T fp16 [n][k]
__device__ __half g_A  [(size_t)BB * NPAIR * KP];      // pair features fp16 (134MB)
__device__ float g_Pt [(size_t)BB * TT * NPAD];
__device__ float g_Pe [(size_t)BB * EE * NPAD];
__device__ float g_part[(size_t)NTILES * BB * NPAIR * 2];

// ---------------- helpers ----------------------------------------------------
__device__ __forceinline__ void mma16816(float* c, const uint32_t* a, const uint32_t* b) {
    asm volatile(
        "mma.sync.aligned.m16n8k16.row.col.f32.f16.f16.f32 "
        "{%0,%1,%2,%3}, {%4,%5,%6,%7}, {%8,%9}, {%0,%1,%2,%3};"
        : "+f"(c[0]), "+f"(c[1]), "+f"(c[2]), "+f"(c[3])
        : "r"(a[0]), "r"(a[1]), "r"(a[2]), "r"(a[3]), "r"(b[0]), "r"(b[1]));
}
__device__ __forceinline__ void ldm_x4(uint32_t* r, uint32_t addr) {
    asm volatile("ldmatrix.sync.aligned.m8n8.x4.shared.b16 {%0,%1,%2,%3}, [%4];"
                 : "=r"(r[0]), "=r"(r[1]), "=r"(r[2]), "=r"(r[3]) : "r"(addr));
}
__device__ __forceinline__ void ldm_x2(uint32_t* r, uint32_t addr) {
    asm volatile("ldmatrix.sync.aligned.m8n8.x2.shared.b16 {%0,%1}, [%2];"
                 : "=r"(r[0]), "=r"(r[1]) : "r"(addr));
}
__device__ __forceinline__ void cp16(uint32_t dst, const void* src) {
    asm volatile("cp.async.ca.shared.global [%0], [%1], 16;" :: "r"(dst), "l"(src) : "memory");
}
__device__ __forceinline__ uint32_t smem_u32(const void* p) {
    uint32_t a;
    asm("{ .reg .u64 t; cvta.to.shared.u64 t, %1; cvt.u32.u64 %0, t; }"
        : "=r"(a) : "l"(p));
    return a;
}
__device__ __forceinline__ uint32_t pack_h2(float lo, float hi) {
    uint32_t r;
    asm("cvt.rn.f16x2.f32 %0, %1, %2;" : "=r"(r) : "f"(hi), "f"(lo));
    return r;
}

// ---------------- kernel 1: wordpiece -> word mean ---------------------------
__global__ void word_mean_kernel(const float* __restrict__ piece,
                                 const int* __restrict__ widx,
                                 float* __restrict__ out) {
    int w = blockIdx.x, b = blockIdx.y;
    int s = widx[(b * WW + w) * 2];
    int e = widx[(b * WW + w) * 2 + 1];
    float inv = 1.0f / (float)(e - s);
    const float* base = piece + (size_t)b * PP * DD;
    int t = threadIdx.x;
    float a0 = 0.f, a1 = 0.f, a2 = 0.f, a3 = 0.f;
    for (int r = s; r < e; r++) {
        float4 v = ((const float4*)(base + (size_t)r * DD))[t];
        a0 += v.x; a1 += v.y; a2 += v.z; a3 += v.w;
    }
    float4 o = make_float4(a0 * inv, a1 * inv, a2 * inv, a3 * inv);
    ((float4*)(out + (size_t)(b * WW + w) * DD))[t] = o;
}

// ---------------- kernel 2: fused span means + W0 transpose-to-fp16 ----------
#define NSPAN ((TT + EE) * BB)   // 1536
__global__ void spans_bprep_kernel(const float* __restrict__ words,
                                   const int* __restrict__ tidx,
                                   const int* __restrict__ eidx,
                                   const float* __restrict__ W0,
                                   float* __restrict__ trig,
                                   float* __restrict__ ent,
                                   __half* __restrict__ W0T) {
    __shared__ float tile[32][33];
    int bid = blockIdx.x;
    if (bid < NSPAN) {
        int m = bid % (TT + EE), b = bid / (TT + EE);
        const int* idx;
        float* out;
        int mm, M;
        if (m < TT) { idx = tidx; out = trig; mm = m; M = TT; }
        else        { idx = eidx; out = ent;  mm = m - TT; M = EE; }
        int s = idx[(b * M + mm) * 2];
        int e = idx[(b * M + mm) * 2 + 1];
        float inv = 1.0f / (float)(e - s);
        const float* base = words + (size_t)b * WW * DD;
        int t = threadIdx.x;
        float a0 = 0.f, a1 = 0.f, a2 = 0.f, a3 = 0.f;
        for (int r = s; r < e; r++) {
            float4 v = ((const float4*)(base + (size_t)r * DD))[t];
            a0 += v.x; a1 += v.y; a2 += v.z; a3 += v.w;
        }
        float4 o = make_float4(a0 * inv, a1 * inv, a2 * inv, a3 * inv);
        ((float4*)(out + (size_t)(b * M + mm) * DD))[t] = o;
    } else {
        int b2 = bid - NSPAN;
        int k0 = (b2 & 127) * 32;
        int n0 = (b2 >> 7) * 32;
        int x = threadIdx.x & 31, y8 = threadIdx.x >> 5;
#pragma unroll
        for (int i = 0; i < 4; i++) {
            int y = y8 + i * 8;
            float v = 0.f;
            if (n0 + x < HH) v = W0[(size_t)(k0 + y) * HH + (n0 + x)];
            tile[y][x] = v;
        }
        __syncthreads();
#pragma unroll
        for (int i = 0; i < 4; i++) {
            int y = y8 + i * 8;
            W0T[(size_t)(n0 + y) * KF + (k0 + x)] = __float2half_rn(tile[x][y]);
        }
    }
}

// ---------------- kernel 3: merged prep = pgemm (60 blocks) + agen (rest) ----
__global__ __launch_bounds__(256)
void prep_kernel(const float* __restrict__ trig,
                 const float* __restrict__ ent,
                 const __half* __restrict__ W0T,
                 const float* __restrict__ b0,
                 float* __restrict__ Pt,
                 float* __restrict__ Pe,
                 __half* __restrict__ A) {
    extern __shared__ char pdsm[];
    int bid = blockIdx.x;
    int tid = threadIdx.x;

    if (bid >= PGEMM_BLOCKS) {
        // ---------------- agen path ----------------
        int bid2 = bid - PGEMM_BLOCKS;
        int b = bid2 >> 10;
        int pair = (bid2 & 1023) * 2 + (tid >> 7);
        int t = pair >> 6, e = pair & 63;
        int lt = tid & 127;
        const float4* tr = (const float4*)(trig + ((size_t)b * TT + t) * DD + lt * 8);
        const float4* er = (const float4*)(ent  + ((size_t)b * EE + e) * DD + lt * 8);
        float4 t0 = tr[0], t1 = tr[1];
        float4 e0 = er[0], e1 = er[1];
        size_t rowo = ((size_t)b * NPAIR + pair) * KP;
        uint4 p;
        p.x = pack_h2(t0.x * e0.x, t0.y * e0.y);
        p.y = pack_h2(t0.z * e0.z, t0.w * e0.w);
        p.z = pack_h2(t1.x * e1.x, t1.y * e1.y);
        p.w = pack_h2(t1.z * e1.z, t1.w * e1.w);
        *(uint4*)(A + rowo + lt * 8) = p;
        uint4 d;
        d.x = pack_h2(fabsf(t0.x - e0.x), fabsf(t0.y - e0.y));
        d.y = pack_h2(fabsf(t0.z - e0.z), fabsf(t0.w - e0.w));
        d.z = pack_h2(fabsf(t1.x - e1.x), fabsf(t1.y - e1.y));
        d.w = pack_h2(fabsf(t1.z - e1.z), fabsf(t1.w - e1.w));
        *(uint4*)(A + rowo + 1024 + lt * 8) = d;
        return;
    }

    // ---------------- pgemm path (double-buffered) ----------------
    uint32_t sb = smem_u32(pdsm);
    int lane = tid & 31, warp = tid >> 5;
    int wm = warp >> 2, wn = warp & 3;
    int g = lane >> 2, t2 = (lane & 3) * 2;
    int nt = bid % NTILES, mtg = bid / NTILES;
    int n0 = nt * 128;

    const float* X;
    float* C;
    const float* bias;
    int m0, koff;
    if (mtg < 4) { X = trig; C = Pt; bias = b0;      m0 = mtg * 128;       koff = 0;  }
    else         { X = ent;  C = Pe; bias = nullptr; m0 = (mtg - 4) * 128; koff = DD; }

    int prow = tid >> 1;
    int cb = (tid & 1) * 32;
    const float* xrow = X + (size_t)(m0 + prow) * DD;
    uint32_t aDst = sb + (uint32_t)prow * PITCH + cb * 2;
    uint32_t bDst = sb + B_OFF + (uint32_t)prow * PITCH + cb * 2;
    const __half* bSrcBase = W0T + (size_t)(n0 + prow) * KF + koff + cb;

    uint32_t aLd = sb + (uint32_t)(wm * 64 + g) * PITCH + (uint32_t)t2 * 2;
    uint32_t bLd = sb + B_OFF + (uint32_t)(wn * 32 + g) * PITCH + (uint32_t)t2 * 2;

    float acc[4][4][4];
#pragma unroll
    for (int i = 0; i < 4; i++)
#pragma unroll
        for (int j = 0; j < 4; j++)
#pragma unroll
            for (int q = 0; q < 4; q++) acc[i][j][q] = 0.f;

    float xv[32];
#pragma unroll
    for (int q = 0; q < 8; q++) {
        float4 v = ((const float4*)(xrow + cb))[q];
        xv[q*4+0] = v.x; xv[q*4+1] = v.y; xv[q*4+2] = v.z; xv[q*4+3] = v.w;
    }
    {
        const char* bs = (const char*)bSrcBase;
#pragma unroll
        for (int q = 0; q < 4; q++)
            cp16(bDst + q * 16, bs + q * 16);
        asm volatile("cp.async.commit_group;" ::: "memory");
    }

    for (int c = 0; c < DD / KC; c++) {
        uint32_t so = (uint32_t)(c & 1) * STAGE_BYTES;
#pragma unroll
        for (int gq = 0; gq < 4; gq++) {
            uint32_t p0 = pack_h2(xv[gq*8+0], xv[gq*8+1]);
            uint32_t p1 = pack_h2(xv[gq*8+2], xv[gq*8+3]);
            uint32_t p2 = pack_h2(xv[gq*8+4], xv[gq*8+5]);
            uint32_t p3 = pack_h2(xv[gq*8+6], xv[gq*8+7]);
            asm volatile("st.shared.v4.b32 [%0], {%1,%2,%3,%4};"
                         :: "r"(aDst + so + gq * 16), "r"(p0), "r"(p1), "r"(p2), "r"(p3) : "memory");
        }
        if (c < DD / KC - 1) {
#pragma unroll
            for (int q = 0; q < 8; q++) {
                float4 v = ((const float4*)(xrow + (c + 1) * KC + cb))[q];
                xv[q*4+0] = v.x; xv[q*4+1] = v.y; xv[q*4+2] = v.z; xv[q*4+3] = v.w;
            }
            uint32_t son = (uint32_t)((c + 1) & 1) * STAGE_BYTES;
            const char* bs = (const char*)(bSrcBase + (c + 1) * KC);
#pragma unroll
            for (int q = 0; q < 4; q++)
                cp16(bDst + son + q * 16, bs + q * 16);
            asm volatile("cp.async.commit_group;" ::: "memory");
            asm volatile("cp.async.wait_group 1;" ::: "memory");
        } else {
            asm volatile("cp.async.wait_group 0;" ::: "memory");
        }
        __syncthreads();
#pragma unroll
        for (int ks = 0; ks < 4; ks++) {
            uint32_t afr[4][4], bfr[4][2];
            uint32_t aO = aLd + so + (uint32_t)ks * 32;
            uint32_t bO = bLd + so + (uint32_t)ks * 32;
#pragma unroll
            for (int j = 0; j < 4; j++) {
                uint32_t o = bO + (uint32_t)j * (8 * PITCH);
                asm volatile("ld.shared.b32 %0, [%1];" : "=r"(bfr[j][0]) : "r"(o));
                asm volatile("ld.shared.b32 %0, [%1];" : "=r"(bfr[j][1]) : "r"(o + 16));
            }
#pragma unroll
            for (int i = 0; i < 4; i++) {
                uint32_t o = aO + (uint32_t)i * (16 * PITCH);
                asm volatile("ld.shared.b32 %0, [%1];" : "=r"(afr[i][0]) : "r"(o));
                asm volatile("ld.shared.b32 %0, [%1];" : "=r"(afr[i][1]) : "r"(o + 8 * PITCH));
                asm volatile("ld.shared.b32 %0, [%1];" : "=r"(afr[i][2]) : "r"(o + 16));
                asm volatile("ld.shared.b32 %0, [%1];" : "=r"(afr[i][3]) : "r"(o + 8 * PITCH + 16));
            }
#pragma unroll
            for (int i = 0; i < 4; i++)
#pragma unroll
                for (int j = 0; j < 4; j++)
                    mma16816(acc[i][j], afr[i], bfr[j]);
        }
        __syncthreads();
    }

#pragma unroll
    for (int j = 0; j < 4; j++) {
        int hcol = n0 + wn * 32 + j * 8 + t2;
#pragma unroll
        for (int cp = 0; cp < 2; cp++) {
            int h = hcol + cp;
            float bb = (bias && h < HH) ? bias[h] : 0.f;
#pragma unroll
            for (int i = 0; i < 4; i++) {
                int r0 = m0 + wm * 64 + i * 16 + g;
                C[(size_t)r0 * NPAD + h]       = acc[i][j][cp] + bb;
                C[(size_t)(r0 + 8) * NPAD + h] = acc[i][j][2 + cp] + bb;
            }
        }
    }
}

// ---------------- kernel 4: pair GEMM (512 thr, 16 warps, 32x32 warp tile) ---
// grid (NTILES, 256). 2 CTAs/SM -> 32 warps/SM. 3-stage cp.async pipeline.
// Warp grid 4x4: wm rows wm*32..+31, wn cols n0 + j*32 + wn*8 (strided).
__global__ __launch_bounds__(512, 2)
void pair_mma_kernel(const __half* __restrict__ A,
                     const __half* __restrict__ W0T,
                     const float* __restrict__ Pt,
                     const float* __restrict__ Pe,
                     const float* __restrict__ W1,
                     float* __restrict__ part) {
    extern __shared__ char dsm[];
    uint32_t sb = smem_u32(dsm);
    int tid = threadIdx.x;
    int lane = tid & 31, warp = tid >> 5;     // warp 0..15
    int wm = warp >> 2, wn = warp & 3;        // 4 x 4
    int g = lane >> 2, t2 = (lane & 3) * 2;
    int nt = blockIdx.x, mtb = blockIdx.y;
    int b = mtb >> 4, mt = mtb & 15;
    int n0 = nt * 128;

    // producer: row = tid>>2 (0..127), 32B segment = (tid&3)*32
    int prow = tid >> 2, pseg = tid & 3;
    const char* aSrc = (const char*)A + ((size_t)mtb * 128 + prow) * (KP * 2) + pseg * 32;
    const char* bSrc = (const char*)W0T + ((size_t)(n0 + prow) * KF + KPOFF) * 2 + pseg * 32;
    uint32_t aDst = sb + (uint32_t)prow * PITCH + pseg * 32;
    uint32_t bDst = aDst + B_OFF;

    // ldmatrix lane addressing
    int sub = lane >> 3, r7 = lane & 7;
    uint32_t aLdm = sb + (uint32_t)(wm * 32 + (sub & 1) * 8 + r7) * PITCH
                       + (uint32_t)((sub >> 1) * 16);
    uint32_t bLdm = sb + B_OFF + (uint32_t)(wn * 8 + r7) * PITCH
                       + (uint32_t)(((lane >> 3) & 1) * 16);

    int nbase_w = n0 + wn * 8;
    int vj0 = nbase_w            < HH;
    int vj1 = nbase_w + 32       < HH;
    int vj2 = nbase_w + 64       < HH;
    int vj3 = nbase_w + 96       < HH;

    float acc[2][4][4];
#pragma unroll
    for (int i = 0; i < 2; i++)
#pragma unroll
        for (int j = 0; j < 4; j++)
#pragma unroll
            for (int q = 0; q < 4; q++) acc[i][j][q] = 0.f;

    // prologue: issue chunks 0,1 into slots 0,1  (2 cp16 A + 2 cp16 B each)
#pragma unroll
    for (int pc = 0; pc < 2; pc++) {
        uint32_t so = (uint32_t)pc * STAGE_BYTES;
#pragma unroll
        for (int q = 0; q < 2; q++) {
            cp16(aDst + so + q * 16, aSrc + pc * 128 + q * 16);
            cp16(bDst + so + q * 16, bSrc + pc * 128 + q * 16);
        }
        asm volatile("cp.async.commit_group;" ::: "memory");
    }

    for (int c = 0; c < NCHUNK; c++) {
        asm volatile("cp.async.wait_group 1;" ::: "memory");
        __syncthreads();
        int cn = c + 2;
        if (cn < NCHUNK) {
            uint32_t so = (uint32_t)(cn % 3) * STAGE_BYTES;
#pragma unroll
            for (int q = 0; q < 2; q++) {
                cp16(aDst + so + q * 16, aSrc + cn * 128 + q * 16);
                cp16(bDst + so + q * 16, bSrc + cn * 128 + q * 16);
            }
        }
        asm volatile("cp.async.commit_group;" ::: "memory");

        uint32_t stageOff = (uint32_t)(c % 3) * STAGE_BYTES;
#pragma unroll
        for (int ks = 0; ks < 4; ks++) {
            uint32_t afr[2][4], bfr[4][2];
            uint32_t aO = aLdm + stageOff + (uint32_t)ks * 32;
            uint32_t bO = bLdm + stageOff + (uint32_t)ks * 32;
            if (vj0) ldm_x2(bfr[0], bO);
            if (vj1) ldm_x2(bfr[1], bO + 32 * PITCH);
            if (vj2) ldm_x2(bfr[2], bO + 64 * PITCH);
            if (vj3) ldm_x2(bfr[3], bO + 96 * PITCH);
#pragma unroll
            for (int i = 0; i < 2; i++)
                ldm_x4(afr[i], aO + (uint32_t)i * (16 * PITCH));
#pragma unroll
            for (int i = 0; i < 2; i++) {
                if (vj0) mma16816(acc[i][0], afr[i], bfr[0]);
                if (vj1) mma16816(acc[i][1], afr[i], bfr[1]);
                if (vj2) mma16816(acc[i][2], afr[i], bfr[2]);
                if (vj3) mma16816(acc[i][3], afr[i], bfr[3]);
            }
        }
    }
    __syncthreads();

    // ---- epilogue: acc + Pt + Pe, relu, @W1 -> per-row partials
    float* red = (float*)dsm;  // [128][4][2]
    float pr[2][2][2];
#pragma unroll
    for (int i = 0; i < 2; i++)
#pragma unroll
        for (int hh = 0; hh < 2; hh++) { pr[i][hh][0] = 0.f; pr[i][hh][1] = 0.f; }

    const float* ptRow = Pt + (size_t)(b * TT + 2 * mt + (wm >> 1)) * NPAD;
    const float* peBase = Pe + (size_t)(b * EE) * NPAD;
    int ebase = (wm & 1) * 32;

#pragma unroll
    for (int j = 0; j < 4; j++) {
        int hcol = n0 + j * 32 + wn * 8 + t2;
#pragma unroll
        for (int cp = 0; cp < 2; cp++) {
            int h = hcol + cp;
            if (h < HH) {
                float pt = ptRow[h];
                float w10 = W1[2 * h], w11 = W1[2 * h + 1];
#pragma unroll
                for (int i = 0; i < 2; i++) {
                    float pe0 = peBase[(size_t)(ebase + i * 16 + g) * NPAD + h];
                    float pe1 = peBase[(size_t)(ebase + i * 16 + g + 8) * NPAD + h];
                    float v0 = fmaxf(acc[i][j][cp] + pt + pe0, 0.f);
                    float v1 = fmaxf(acc[i][j][2 + cp] + pt + pe1, 0.f);
                    pr[i][0][0] = fmaf(v0, w10, pr[i][0][0]);
                    pr[i][0][1] = fmaf(v0, w11, pr[i][0][1]);
                    pr[i][1][0] = fmaf(v1, w10, pr[i][1][0]);
                    pr[i][1][1] = fmaf(v1, w11, pr[i][1][1]);
                }
            }
        }
    }
#pragma unroll
    for (int i = 0; i < 2; i++)
#pragma unroll
        for (int hh = 0; hh < 2; hh++)
#pragma unroll
            for (int o = 0; o < 2; o++) {
                float v = pr[i][hh][o];
                v += __shfl_xor_sync(0xffffffffu, v, 1);
                v += __shfl_xor_sync(0xffffffffu, v, 2);
                pr[i][hh][o] = v;
            }
    if ((lane & 3) == 0) {
#pragma unroll
        for (int i = 0; i < 2; i++)
#pragma unroll
            for (int hh = 0; hh < 2; hh++) {
                int row = wm * 32 + i * 16 + g + hh * 8;
                red[(row * 4 + wn) * 2 + 0] = pr[i][hh][0];
                red[(row * 4 + wn) * 2 + 1] = pr[i][hh][1];
            }
    }
    __syncthreads();
    if (tid < 128) {
        int row = tid;
        float a0 = 0.f, a1 = 0.f;
#pragma unroll
        for (int wc = 0; wc < 4; wc++) {
            a0 += red[(row * 4 + wc) * 2 + 0];
            a1 += red[(row * 4 + wc) * 2 + 1];
        }
        int pair = (2 * mt + (row >> 6)) * EE + (row & 63);
        size_t oidx = ((size_t)nt * BB * NPAIR + (size_t)b * NPAIR + pair) * 2;
        part[oidx]     = a0;
        part[oidx + 1] = a1;
    }
}

// ---------------- kernel 5: reduce 5 partials + b1 ---------------------------
__global__ void reduce_out_kernel(const float* __restrict__ part,
                                  const float* __restrict__ b1,
                                  float* __restrict__ out) {
    int i = blockIdx.x * blockDim.x + threadIdx.x;
    float a = b1[i & 1];
#pragma unroll
    for (int t = 0; t < NTILES; t++)
        a += part[(size_t)t * BB * NPAIR * 2 + i];
    out[i] = a;
}

// ---------------- launch -----------------------------------------------------
extern "C" void kernel_launch(void* const* d_in, const int* in_sizes, int n_in,
                              void* d_out, int out_size) {
    const float* piece = (const float*)d_in[0];
    const int*   widx  = (const int*)d_in[1];
    const int*   tidx  = (const int*)d_in[2];
    const int*   eidx  = (const int*)d_in[3];
    const float* W0    = (const float*)d_in[4];
    const float* b0    = (const float*)d_in[5];
    const float* W1    = (const float*)d_in[6];
    const float* b1    = (const float*)d_in[7];
    float* out = (float*)d_out;

    float *wordp, *trigp, *entp, *ptp, *pep, *partp;
    __half *w0tp, *ap;
    cudaGetSymbolAddress((void**)&wordp, g_word);
    cudaGetSymbolAddress((void**)&trigp, g_trig);
    cudaGetSymbolAddress((void**)&entp,  g_ent);
    cudaGetSymbolAddress((void**)&w0tp,  g_W0T);
    cudaGetSymbolAddress((void**)&ap,    g_A);
    cudaGetSymbolAddress((void**)&ptp,   g_Pt);
    cudaGetSymbolAddress((void**)&pep,   g_Pe);
    cudaGetSymbolAddress((void**)&partp, g_part);

    cudaFuncSetAttribute(pair_mma_kernel,
                         cudaFuncAttributeMaxDynamicSharedMemorySize, SMEM_DYN);
    cudaFuncSetAttribute(prep_kernel,
                         cudaFuncAttributeMaxDynamicSharedMemorySize, PGEMM_SMEM);

    word_mean_kernel<<<dim3(WW, BB), 256>>>(piece, widx, wordp);
    spans_bprep_kernel<<<NSPAN + (KF / 32) * (NPAD / 32), 256>>>(
        wordp, tidx, eidx, W0, trigp, entp, w0tp);
    prep_kernel<<<PGEMM_BLOCKS + (NPAIR / 2) * BB, 256, PGEMM_SMEM>>>(
        trigp, entp, w0tp, b0, ptp, pep, ap);
    pair_mma_kernel<<<dim3(NTILES, 256), 512, SMEM_DYN>>>(
        ap, w0tp, ptp, pep, W1, partp);
    reduce_out_kernel<<<(BB * NPAIR * 2) / 1024, 1024>>>(partp, b1, out);
    (void)in_sizes; (void)n_in; (void)out_size;
}

// round 14
// speedup vs baseline: 1.2782x; 1.0369x over previous
#include <cuda_runtime.h>
#include <cuda_fp16.h>
#include <math.h>
#include <stdint.h>

// Problem constants
#define BB 16
#define PP 512
#define DD 1024
#define WW 400
#define TT 32
#define EE 64
#define HH 600
#define NPAIR (TT * EE)     // 2048
#define KF 4096             // W0T row length
#define KPOFF 2048          // pair-GEMM feature base: [t*e | |t-e|]
#define KP 2048             // pair-GEMM K
#define NPAD 640
#define KC 64               // k per chunk
#define NCHUNK 32           // KP / KC
#define NTILES 5            // h tiles of 128

// smem geometry (bytes): stage = A[128][64h] + B[128][64h], pitch 144
#define PITCH 144
#define B_OFF (128 * PITCH)               // 18432
#define STAGE_BYTES (2 * 128 * PITCH)     // 36864
#define NSTAGE 3
#define SMEM_DYN (NSTAGE * STAGE_BYTES)   // 110592
#define PGEMM_SMEM (2 * STAGE_BYTES)      // 73728
#define PGEMM_BLOCKS (NTILES * 12)        // 60

// ---------------- scratch ----------------------------------------------------
__device__ float g_word[(size_t)BB * WW * DD];
__device__ float g_trig[(size_t)BB * TT * DD];
__device__ float g_ent [(size_t)BB * EE * DD];
__device__ __half g_W0T[(size_t)NPAD * KF];            // W0^T fp16 [n][k]
__device__ __half g_A  [(size_t)BB * NPAIR * KP];      // pair features fp16 (134MB)
__device__ float g_Pt [(size_t)BB * TT * NPAD];
__device__ float g_Pe [(size_t)BB * EE * NPAD];
__device__ float g_part[(size_t)NTILES * BB * NPAIR * 2];

// ---------------- helpers ----------------------------------------------------
__device__ __forceinline__ void mma16816(float* c, const uint32_t* a, const uint32_t* b) {
    asm volatile(
        "mma.sync.aligned.m16n8k16.row.col.f32.f16.f16.f32 "
        "{%0,%1,%2,%3}, {%4,%5,%6,%7}, {%8,%9}, {%0,%1,%2,%3};"
        : "+f"(c[0]), "+f"(c[1]), "+f"(c[2]), "+f"(c[3])
        : "r"(a[0]), "r"(a[1]), "r"(a[2]), "r"(a[3]), "r"(b[0]), "r"(b[1]));
}
__device__ __forceinline__ void ldm_x4(uint32_t* r, uint32_t addr) {
    asm volatile("ldmatrix.sync.aligned.m8n8.x4.shared.b16 {%0,%1,%2,%3}, [%4];"
                 : "=r"(r[0]), "=r"(r[1]), "=r"(r[2]), "=r"(r[3]) : "r"(addr));
}
__device__ __forceinline__ void ldm_x2(uint32_t* r, uint32_t addr) {
    asm volatile("ldmatrix.sync.aligned.m8n8.x2.shared.b16 {%0,%1}, [%2];"
                 : "=r"(r[0]), "=r"(r[1]) : "r"(addr));
}
__device__ __forceinline__ void cp16(uint32_t dst, const void* src) {
    asm volatile("cp.async.ca.shared.global [%0], [%1], 16;" :: "r"(dst), "l"(src) : "memory");
}
__device__ __forceinline__ uint32_t smem_u32(const void* p) {
    uint32_t a;
    asm("{ .reg .u64 t; cvta.to.shared.u64 t, %1; cvt.u32.u64 %0, t; }"
        : "=r"(a) : "l"(p));
    return a;
}
__device__ __forceinline__ uint32_t pack_h2(float lo, float hi) {
    uint32_t r;
    asm("cvt.rn.f16x2.f32 %0, %1, %2;" : "=r"(r) : "f"(hi), "f"(lo));
    return r;
}

// ---------------- kernel 1: wordpiece -> word mean ---------------------------
__global__ void word_mean_kernel(const float* __restrict__ piece,
                                 const int* __restrict__ widx,
                                 float* __restrict__ out) {
    int w = blockIdx.x, b = blockIdx.y;
    int s = widx[(b * WW + w) * 2];
    int e = widx[(b * WW + w) * 2 + 1];
    float inv = 1.0f / (float)(e - s);
    const float* base = piece + (size_t)b * PP * DD;
    int t = threadIdx.x;
    float a0 = 0.f, a1 = 0.f, a2 = 0.f, a3 = 0.f;
    for (int r = s; r < e; r++) {
        float4 v = ((const float4*)(base + (size_t)r * DD))[t];
        a0 += v.x; a1 += v.y; a2 += v.z; a3 += v.w;
    }
    float4 o = make_float4(a0 * inv, a1 * inv, a2 * inv, a3 * inv);
    ((float4*)(out + (size_t)(b * WW + w) * DD))[t] = o;
}

// ---------------- kernel 2: fused span means + W0 transpose-to-fp16 ----------
#define NSPAN ((TT + EE) * BB)   // 1536
__global__ void spans_bprep_kernel(const float* __restrict__ words,
                                   const int* __restrict__ tidx,
                                   const int* __restrict__ eidx,
                                   const float* __restrict__ W0,
                                   float* __restrict__ trig,
                                   float* __restrict__ ent,
                                   __half* __restrict__ W0T) {
    __shared__ float tile[32][33];
    int bid = blockIdx.x;
    if (bid < NSPAN) {
        int m = bid % (TT + EE), b = bid / (TT + EE);
        const int* idx;
        float* out;
        int mm, M;
        if (m < TT) { idx = tidx; out = trig; mm = m; M = TT; }
        else        { idx = eidx; out = ent;  mm = m - TT; M = EE; }
        int s = idx[(b * M + mm) * 2];
        int e = idx[(b * M + mm) * 2 + 1];
        float inv = 1.0f / (float)(e - s);
        const float* base = words + (size_t)b * WW * DD;
        int t = threadIdx.x;
        float a0 = 0.f, a1 = 0.f, a2 = 0.f, a3 = 0.f;
        for (int r = s; r < e; r++) {
            float4 v = ((const float4*)(base + (size_t)r * DD))[t];
            a0 += v.x; a1 += v.y; a2 += v.z; a3 += v.w;
        }
        float4 o = make_float4(a0 * inv, a1 * inv, a2 * inv, a3 * inv);
        ((float4*)(out + (size_t)(b * M + mm) * DD))[t] = o;
    } else {
        int b2 = bid - NSPAN;
        int k0 = (b2 & 127) * 32;
        int n0 = (b2 >> 7) * 32;
        int x = threadIdx.x & 31, y8 = threadIdx.x >> 5;
#pragma unroll
        for (int i = 0; i < 4; i++) {
            int y = y8 + i * 8;
            float v = 0.f;
            if (n0 + x < HH) v = W0[(size_t)(k0 + y) * HH + (n0 + x)];
            tile[y][x] = v;
        }
        __syncthreads();
#pragma unroll
        for (int i = 0; i < 4; i++) {
            int y = y8 + i * 8;
            W0T[(size_t)(n0 + y) * KF + (k0 + x)] = __float2half_rn(tile[x][y]);
        }
    }
}

// ---------------- kernel 3: merged prep = pgemm (60 blocks) + agen (rest) ----
__global__ __launch_bounds__(256)
void prep_kernel(const float* __restrict__ trig,
                 const float* __restrict__ ent,
                 const __half* __restrict__ W0T,
                 const float* __restrict__ b0,
                 float* __restrict__ Pt,
                 float* __restrict__ Pe,
                 __half* __restrict__ A) {
    extern __shared__ char pdsm[];
    int bid = blockIdx.x;
    int tid = threadIdx.x;

    if (bid >= PGEMM_BLOCKS) {
        // ---------------- agen path ----------------
        int bid2 = bid - PGEMM_BLOCKS;
        int b = bid2 >> 10;
        int pair = (bid2 & 1023) * 2 + (tid >> 7);
        int t = pair >> 6, e = pair & 63;
        int lt = tid & 127;
        const float4* tr = (const float4*)(trig + ((size_t)b * TT + t) * DD + lt * 8);
        const float4* er = (const float4*)(ent  + ((size_t)b * EE + e) * DD + lt * 8);
        float4 t0 = tr[0], t1 = tr[1];
        float4 e0 = er[0], e1 = er[1];
        size_t rowo = ((size_t)b * NPAIR + pair) * KP;
        uint4 p;
        p.x = pack_h2(t0.x * e0.x, t0.y * e0.y);
        p.y = pack_h2(t0.z * e0.z, t0.w * e0.w);
        p.z = pack_h2(t1.x * e1.x, t1.y * e1.y);
        p.w = pack_h2(t1.z * e1.z, t1.w * e1.w);
        *(uint4*)(A + rowo + lt * 8) = p;
        uint4 d;
        d.x = pack_h2(fabsf(t0.x - e0.x), fabsf(t0.y - e0.y));
        d.y = pack_h2(fabsf(t0.z - e0.z), fabsf(t0.w - e0.w));
        d.z = pack_h2(fabsf(t1.x - e1.x), fabsf(t1.y - e1.y));
        d.w = pack_h2(fabsf(t1.z - e1.z), fabsf(t1.w - e1.w));
        *(uint4*)(A + rowo + 1024 + lt * 8) = d;
        return;
    }

    // ---------------- pgemm path (double-buffered) ----------------
    uint32_t sb = smem_u32(pdsm);
    int lane = tid & 31, warp = tid >> 5;
    int wm = warp >> 2, wn = warp & 3;
    int g = lane >> 2, t2 = (lane & 3) * 2;
    int nt = bid % NTILES, mtg = bid / NTILES;
    int n0 = nt * 128;

    const float* X;
    float* C;
    const float* bias;
    int m0, koff;
    if (mtg < 4) { X = trig; C = Pt; bias = b0;      m0 = mtg * 128;       koff = 0;  }
    else         { X = ent;  C = Pe; bias = nullptr; m0 = (mtg - 4) * 128; koff = DD; }

    int prow = tid >> 1;
    int cb = (tid & 1) * 32;
    const float* xrow = X + (size_t)(m0 + prow) * DD;
    uint32_t aDst = sb + (uint32_t)prow * PITCH + cb * 2;
    uint32_t bDst = sb + B_OFF + (uint32_t)prow * PITCH + cb * 2;
    const __half* bSrcBase = W0T + (size_t)(n0 + prow) * KF + koff + cb;

    uint32_t aLd = sb + (uint32_t)(wm * 64 + g) * PITCH + (uint32_t)t2 * 2;
    uint32_t bLd = sb + B_OFF + (uint32_t)(wn * 32 + g) * PITCH + (uint32_t)t2 * 2;

    float acc[4][4][4];
#pragma unroll
    for (int i = 0; i < 4; i++)
#pragma unroll
        for (int j = 0; j < 4; j++)
#pragma unroll
            for (int q = 0; q < 4; q++) acc[i][j][q] = 0.f;

    float xv[32];
#pragma unroll
    for (int q = 0; q < 8; q++) {
        float4 v = ((const float4*)(xrow + cb))[q];
        xv[q*4+0] = v.x; xv[q*4+1] = v.y; xv[q*4+2] = v.z; xv[q*4+3] = v.w;
    }
    {
        const char* bs = (const char*)bSrcBase;
#pragma unroll
        for (int q = 0; q < 4; q++)
            cp16(bDst + q * 16, bs + q * 16);
        asm volatile("cp.async.commit_group;" ::: "memory");
    }

    for (int c = 0; c < DD / KC; c++) {
        uint32_t so = (uint32_t)(c & 1) * STAGE_BYTES;
#pragma unroll
        for (int gq = 0; gq < 4; gq++) {
            uint32_t p0 = pack_h2(xv[gq*8+0], xv[gq*8+1]);
            uint32_t p1 = pack_h2(xv[gq*8+2], xv[gq*8+3]);
            uint32_t p2 = pack_h2(xv[gq*8+4], xv[gq*8+5]);
            uint32_t p3 = pack_h2(xv[gq*8+6], xv[gq*8+7]);
            asm volatile("st.shared.v4.b32 [%0], {%1,%2,%3,%4};"
                         :: "r"(aDst + so + gq * 16), "r"(p0), "r"(p1), "r"(p2), "r"(p3) : "memory");
        }
        if (c < DD / KC - 1) {
#pragma unroll
            for (int q = 0; q < 8; q++) {
                float4 v = ((const float4*)(xrow + (c + 1) * KC + cb))[q];
                xv[q*4+0] = v.x; xv[q*4+1] = v.y; xv[q*4+2] = v.z; xv[q*4+3] = v.w;
            }
            uint32_t son = (uint32_t)((c + 1) & 1) * STAGE_BYTES;
            const char* bs = (const char*)(bSrcBase + (c + 1) * KC);
#pragma unroll
            for (int q = 0; q < 4; q++)
                cp16(bDst + son + q * 16, bs + q * 16);
            asm volatile("cp.async.commit_group;" ::: "memory");
            asm volatile("cp.async.wait_group 1;" ::: "memory");
        } else {
            asm volatile("cp.async.wait_group 0;" ::: "memory");
        }
        __syncthreads();
#pragma unroll
        for (int ks = 0; ks < 4; ks++) {
            uint32_t afr[4][4], bfr[4][2];
            uint32_t aO = aLd + so + (uint32_t)ks * 32;
            uint32_t bO = bLd + so + (uint32_t)ks * 32;
#pragma unroll
            for (int j = 0; j < 4; j++) {
                uint32_t o = bO + (uint32_t)j * (8 * PITCH);
                asm volatile("ld.shared.b32 %0, [%1];" : "=r"(bfr[j][0]) : "r"(o));
                asm volatile("ld.shared.b32 %0, [%1];" : "=r"(bfr[j][1]) : "r"(o + 16));
            }
#pragma unroll
            for (int i = 0; i < 4; i++) {
                uint32_t o = aO + (uint32_t)i * (16 * PITCH);
                asm volatile("ld.shared.b32 %0, [%1];" : "=r"(afr[i][0]) : "r"(o));
                asm volatile("ld.shared.b32 %0, [%1];" : "=r"(afr[i][1]) : "r"(o + 8 * PITCH));
                asm volatile("ld.shared.b32 %0, [%1];" : "=r"(afr[i][2]) : "r"(o + 16));
                asm volatile("ld.shared.b32 %0, [%1];" : "=r"(afr[i][3]) : "r"(o + 8 * PITCH + 16));
            }
#pragma unroll
            for (int i = 0; i < 4; i++)
#pragma unroll
                for (int j = 0; j < 4; j++)
                    mma16816(acc[i][j], afr[i], bfr[j]);
        }
        __syncthreads();
    }

#pragma unroll
    for (int j = 0; j < 4; j++) {
        int hcol = n0 + wn * 32 + j * 8 + t2;
#pragma unroll
        for (int cp = 0; cp < 2; cp++) {
            int h = hcol + cp;
            float bb = (bias && h < HH) ? bias[h] : 0.f;
#pragma unroll
            for (int i = 0; i < 4; i++) {
                int r0 = m0 + wm * 64 + i * 16 + g;
                C[(size_t)r0 * NPAD + h]       = acc[i][j][cp] + bb;
                C[(size_t)(r0 + 8) * NPAD + h] = acc[i][j][2 + cp] + bb;
            }
        }
    }
}

// ---------------- kernel 4: pair GEMM (512 thr, tail-aware 1D grid) ----------
// grid 1280 1D: bid<1024 -> heavy tiles nt=bid&3 (full N), mtb=bid>>2;
//               bid>=1024 -> light tiles nt=4 (N-trimmed), mtb=bid-1024.
// Last wave (96 CTAs) is all-light -> shorter tail. 2 CTAs/SM, 32 warps.
__global__ __launch_bounds__(512, 2)
void pair_mma_kernel(const __half* __restrict__ A,
                     const __half* __restrict__ W0T,
                     const float* __restrict__ Pt,
                     const float* __restrict__ Pe,
                     const float* __restrict__ W1,
                     float* __restrict__ part) {
    extern __shared__ char dsm[];
    uint32_t sb = smem_u32(dsm);
    int tid = threadIdx.x;
    int lane = tid & 31, warp = tid >> 5;     // warp 0..15
    int wm = warp >> 2, wn = warp & 3;        // 4 x 4
    int g = lane >> 2, t2 = (lane & 3) * 2;

    int bid = blockIdx.x;
    int nt, mtb;
    if (bid < 1024) { nt = bid & 3; mtb = bid >> 2; }
    else            { nt = 4;       mtb = bid - 1024; }
    int b = mtb >> 4, mt = mtb & 15;
    int n0 = nt * 128;

    // producer: row = tid>>2 (0..127), 32B segment = (tid&3)*32
    int prow = tid >> 2, pseg = tid & 3;
    const char* aSrc = (const char*)A + ((size_t)mtb * 128 + prow) * (KP * 2) + pseg * 32;
    const char* bSrc = (const char*)W0T + ((size_t)(n0 + prow) * KF + KPOFF) * 2 + pseg * 32;
    uint32_t aDst = sb + (uint32_t)prow * PITCH + pseg * 32;
    uint32_t bDst = aDst + B_OFF;

    // ldmatrix lane addressing
    int sub = lane >> 3, r7 = lane & 7;
    uint32_t aLdm = sb + (uint32_t)(wm * 32 + (sub & 1) * 8 + r7) * PITCH
                       + (uint32_t)((sub >> 1) * 16);
    uint32_t bLdm = sb + B_OFF + (uint32_t)(wn * 8 + r7) * PITCH
                       + (uint32_t)(((lane >> 3) & 1) * 16);

    int nbase_w = n0 + wn * 8;
    int vj0 = nbase_w            < HH;
    int vj1 = nbase_w + 32       < HH;
    int vj2 = nbase_w + 64       < HH;
    int vj3 = nbase_w + 96       < HH;

    float acc[2][4][4];
#pragma unroll
    for (int i = 0; i < 2; i++)
#pragma unroll
        for (int j = 0; j < 4; j++)
#pragma unroll
            for (int q = 0; q < 4; q++) acc[i][j][q] = 0.f;

    // prologue: issue chunks 0,1 into slots 0,1
#pragma unroll
    for (int pc = 0; pc < 2; pc++) {
        uint32_t so = (uint32_t)pc * STAGE_BYTES;
#pragma unroll
        for (int q = 0; q < 2; q++) {
            cp16(aDst + so + q * 16, aSrc + pc * 128 + q * 16);
            cp16(bDst + so + q * 16, bSrc + pc * 128 + q * 16);
        }
        asm volatile("cp.async.commit_group;" ::: "memory");
    }

    for (int c = 0; c < NCHUNK; c++) {
        asm volatile("cp.async.wait_group 1;" ::: "memory");
        __syncthreads();
        int cn = c + 2;
        if (cn < NCHUNK) {
            uint32_t so = (uint32_t)(cn % 3) * STAGE_BYTES;
#pragma unroll
            for (int q = 0; q < 2; q++) {
                cp16(aDst + so + q * 16, aSrc + cn * 128 + q * 16);
                cp16(bDst + so + q * 16, bSrc + cn * 128 + q * 16);
            }
        }
        asm volatile("cp.async.commit_group;" ::: "memory");

        uint32_t stageOff = (uint32_t)(c % 3) * STAGE_BYTES;
#pragma unroll
        for (int ks = 0; ks < 4; ks++) {
            uint32_t afr[2][4], bfr[4][2];
            uint32_t aO = aLdm + stageOff + (uint32_t)ks * 32;
            uint32_t bO = bLdm + stageOff + (uint32_t)ks * 32;
            if (vj0) ldm_x2(bfr[0], bO);
            if (vj1) ldm_x2(bfr[1], bO + 32 * PITCH);
            if (vj2) ldm_x2(bfr[2], bO + 64 * PITCH);
            if (vj3) ldm_x2(bfr[3], bO + 96 * PITCH);
#pragma unroll
            for (int i = 0; i < 2; i++)
                ldm_x4(afr[i], aO + (uint32_t)i * (16 * PITCH));
#pragma unroll
            for (int i = 0; i < 2; i++) {
                if (vj0) mma16816(acc[i][0], afr[i], bfr[0]);
                if (vj1) mma16816(acc[i][1], afr[i], bfr[1]);
                if (vj2) mma16816(acc[i][2], afr[i], bfr[2]);
                if (vj3) mma16816(acc[i][3], afr[i], bfr[3]);
            }
        }
    }
    __syncthreads();

    // ---- epilogue: acc + Pt + Pe, relu, @W1 -> per-row partials
    float* red = (float*)dsm;  // [128][4][2]
    float pr[2][2][2];
#pragma unroll
    for (int i = 0; i < 2; i++)
#pragma unroll
        for (int hh = 0; hh < 2; hh++) { pr[i][hh][0] = 0.f; pr[i][hh][1] = 0.f; }

    const float* ptRow = Pt + (size_t)(b * TT + 2 * mt + (wm >> 1)) * NPAD;
    const float* peBase = Pe + (size_t)(b * EE) * NPAD;
    int ebase = (wm & 1) * 32;

#pragma unroll
    for (int j = 0; j < 4; j++) {
        int hcol = n0 + j * 32 + wn * 8 + t2;
#pragma unroll
        for (int cp = 0; cp < 2; cp++) {
            int h = hcol + cp;
            if (h < HH) {
                float pt = ptRow[h];
                float w10 = W1[2 * h], w11 = W1[2 * h + 1];
#pragma unroll
                for (int i = 0; i < 2; i++) {
                    float pe0 = peBase[(size_t)(ebase + i * 16 + g) * NPAD + h];
                    float pe1 = peBase[(size_t)(ebase + i * 16 + g + 8) * NPAD + h];
                    float v0 = fmaxf(acc[i][j][cp] + pt + pe0, 0.f);
                    float v1 = fmaxf(acc[i][j][2 + cp] + pt + pe1, 0.f);
                    pr[i][0][0] = fmaf(v0, w10, pr[i][0][0]);
                    pr[i][0][1] = fmaf(v0, w11, pr[i][0][1]);
                    pr[i][1][0] = fmaf(v1, w10, pr[i][1][0]);
                    pr[i][1][1] = fmaf(v1, w11, pr[i][1][1]);
                }
            }
        }
    }
#pragma unroll
    for (int i = 0; i < 2; i++)
#pragma unroll
        for (int hh = 0; hh < 2; hh++)
#pragma unroll
            for (int o = 0; o < 2; o++) {
                float v = pr[i][hh][o];
                v += __shfl_xor_sync(0xffffffffu, v, 1);
                v += __shfl_xor_sync(0xffffffffu, v, 2);
                pr[i][hh][o] = v;
            }
    if ((lane & 3) == 0) {
#pragma unroll
        for (int i = 0; i < 2; i++)
#pragma unroll
            for (int hh = 0; hh < 2; hh++) {
                int row = wm * 32 + i * 16 + g + hh * 8;
                red[(row * 4 + wn) * 2 + 0] = pr[i][hh][0];
                red[(row * 4 + wn) * 2 + 1] = pr[i][hh][1];
            }
    }
    __syncthreads();
    if (tid < 128) {
        int row = tid;
        float a0 = 0.f, a1 = 0.f;
#pragma unroll
        for (int wc = 0; wc < 4; wc++) {
            a0 += red[(row * 4 + wc) * 2 + 0];
            a1 += red[(row * 4 + wc) * 2 + 1];
        }
        int pair = (2 * mt + (row >> 6)) * EE + (row & 63);
        size_t oidx = ((size_t)nt * BB * NPAIR + (size_t)b * NPAIR + pair) * 2;
        part[oidx]     = a0;
        part[oidx + 1] = a1;
    }
}

// ---------------- kernel 5: reduce 5 partials + b1 ---------------------------
__global__ void reduce_out_kernel(const float* __restrict__ part,
                                  const float* __restrict__ b1,
                                  float* __restrict__ out) {
    int i = blockIdx.x * blockDim.x + threadIdx.x;
    float a = b1[i & 1];
#pragma unroll
    for (int t = 0; t < NTILES; t++)
        a += part[(size_t)t * BB * NPAIR * 2 + i];
    out[i] = a;
}

// ---------------- launch -----------------------------------------------------
extern "C" void kernel_launch(void* const* d_in, const int* in_sizes, int n_in,
                              void* d_out, int out_size) {
    const float* piece = (const float*)d_in[0];
    const int*   widx  = (const int*)d_in[1];
    const int*   tidx  = (const int*)d_in[2];
    const int*   eidx  = (const int*)d_in[3];
    const float* W0    = (const float*)d_in[4];
    const float* b0    = (const float*)d_in[5];
    const float* W1    = (const float*)d_in[6];
    const float* b1    = (const float*)d_in[7];
    float* out = (float*)d_out;

    float *wordp, *trigp, *entp, *ptp, *pep, *partp;
    __half *w0tp, *ap;
    cudaGetSymbolAddress((void**)&wordp, g_word);
    cudaGetSymbolAddress((void**)&trigp, g_trig);
    cudaGetSymbolAddress((void**)&entp,  g_ent);
    cudaGetSymbolAddress((void**)&w0tp,  g_W0T);
    cudaGetSymbolAddress((void**)&ap,    g_A);
    cudaGetSymbolAddress((void**)&ptp,   g_Pt);
    cudaGetSymbolAddress((void**)&pep,   g_Pe);
    cudaGetSymbolAddress((void**)&partp, g_part);

    cudaFuncSetAttribute(pair_mma_kernel,
                         cudaFuncAttributeMaxDynamicSharedMemorySize, SMEM_DYN);
    cudaFuncSetAttribute(prep_kernel,
                         cudaFuncAttributeMaxDynamicSharedMemorySize, PGEMM_SMEM);

    word_mean_kernel<<<dim3(WW, BB), 256>>>(piece, widx, wordp);
    spans_bprep_kernel<<<NSPAN + (KF / 32) * (NPAD / 32), 256>>>(
        wordp, tidx, eidx, W0, trigp, entp, w0tp);
    prep_kernel<<<PGEMM_BLOCKS + (NPAIR / 2) * BB, 256, PGEMM_SMEM>>>(
        trigp, entp, w0tp, b0, ptp, pep, ap);
    pair_mma_kernel<<<NTILES * 256, 512, SMEM_DYN>>>(
        ap, w0tp, ptp, pep, W1, partp);
    reduce_out_kernel<<<(BB * NPAIR * 2) / 1024, 1024>>>(partp, b1, out);
    (void)in_sizes; (void)n_in; (void)out_size;
}

// round 15
// speedup vs baseline: 1.2889x; 1.0084x over previous
#include <cuda_runtime.h>
#include <cuda_fp16.h>
#include <math.h>
#include <stdint.h>

// Problem constants
#define BB 16
#define PP 512
#define DD 1024
#define WW 400
#define TT 32
#define EE 64
#define HH 600
#define NPAIR (TT * EE)     // 2048
#define KF 4096             // W0T row length
#define KPOFF 2048          // pair-GEMM feature base: [t*e | |t-e|]
#define KP 2048             // pair-GEMM K
#define NPAD 640
#define KC 64               // k per chunk
#define NCHUNK 32           // KP / KC
#define NTILES 5            // h tiles of 128

// smem geometry (bytes): stage = A[128][64h] + B[128][64h], pitch 144
#define PITCH 144
#define B_OFF (128 * PITCH)               // 18432
#define STAGE_BYTES (2 * 128 * PITCH)     // 36864
#define NSTAGE 3
#define SMEM_DYN (NSTAGE * STAGE_BYTES)   // 110592
#define PGEMM_SMEM (2 * STAGE_BYTES)      // 73728
#define PGEMM_BLOCKS (NTILES * 12)        // 60
#define NWORD (WW * BB)                   // 6400

// ---------------- scratch ----------------------------------------------------
__device__ float g_word[(size_t)BB * WW * DD];
__device__ float g_trig[(size_t)BB * TT * DD];
__device__ float g_ent [(size_t)BB * EE * DD];
__device__ __half g_W0T[(size_t)NPAD * KF];            // W0^T fp16 [n][k]
__device__ __half g_A  [(size_t)BB * NPAIR * KP];      // pair features fp16 (134MB)
__device__ float g_Pt [(size_t)BB * TT * NPAD];
__device__ float g_Pe [(size_t)BB * EE * NPAD];
__device__ float g_part[(size_t)NTILES * BB * NPAIR * 2];

// ---------------- helpers ----------------------------------------------------
__device__ __forceinline__ void mma16816(float* c, const uint32_t* a, const uint32_t* b) {
    asm volatile(
        "mma.sync.aligned.m16n8k16.row.col.f32.f16.f16.f32 "
        "{%0,%1,%2,%3}, {%4,%5,%6,%7}, {%8,%9}, {%0,%1,%2,%3};"
        : "+f"(c[0]), "+f"(c[1]), "+f"(c[2]), "+f"(c[3])
        : "r"(a[0]), "r"(a[1]), "r"(a[2]), "r"(a[3]), "r"(b[0]), "r"(b[1]));
}
__device__ __forceinline__ void ldm_x4(uint32_t* r, uint32_t addr) {
    asm volatile("ldmatrix.sync.aligned.m8n8.x4.shared.b16 {%0,%1,%2,%3}, [%4];"
                 : "=r"(r[0]), "=r"(r[1]), "=r"(r[2]), "=r"(r[3]) : "r"(addr));
}
__device__ __forceinline__ void cp16(uint32_t dst, const void* src) {
    asm volatile("cp.async.ca.shared.global [%0], [%1], 16;" :: "r"(dst), "l"(src) : "memory");
}
__device__ __forceinline__ uint32_t smem_u32(const void* p) {
    uint32_t a;
    asm("{ .reg .u64 t; cvta.to.shared.u64 t, %1; cvt.u32.u64 %0, t; }"
        : "=r"(a) : "l"(p));
    return a;
}
__device__ __forceinline__ uint32_t pack_h2(float lo, float hi) {
    uint32_t r;
    asm("cvt.rn.f16x2.f32 %0, %1, %2;" : "=r"(r) : "f"(hi), "f"(lo));
    return r;
}

// ---------------- kernel 1: word means + W0 transpose (independent, merged) --
__global__ void word_bprep_kernel(const float* __restrict__ piece,
                                  const int* __restrict__ widx,
                                  const float* __restrict__ W0,
                                  float* __restrict__ out,
                                  __half* __restrict__ W0T) {
    __shared__ float tile[32][33];
    int bid = blockIdx.x;
    if (bid < NWORD) {
        int w = bid % WW, b = bid / WW;
        int s = widx[(b * WW + w) * 2];
        int e = widx[(b * WW + w) * 2 + 1];
        float inv = 1.0f / (float)(e - s);
        const float* base = piece + (size_t)b * PP * DD;
        int t = threadIdx.x;
        float a0 = 0.f, a1 = 0.f, a2 = 0.f, a3 = 0.f;
        for (int r = s; r < e; r++) {
            float4 v = ((const float4*)(base + (size_t)r * DD))[t];
            a0 += v.x; a1 += v.y; a2 += v.z; a3 += v.w;
        }
        float4 o = make_float4(a0 * inv, a1 * inv, a2 * inv, a3 * inv);
        ((float4*)(out + (size_t)(b * WW + w) * DD))[t] = o;
    } else {
        int b2 = bid - NWORD;               // 0..2559
        int k0 = (b2 & 127) * 32;
        int n0 = (b2 >> 7) * 32;
        int x = threadIdx.x & 31, y8 = threadIdx.x >> 5;
#pragma unroll
        for (int i = 0; i < 4; i++) {
            int y = y8 + i * 8;
            float v = 0.f;
            if (n0 + x < HH) v = W0[(size_t)(k0 + y) * HH + (n0 + x)];
            tile[y][x] = v;
        }
        __syncthreads();
#pragma unroll
        for (int i = 0; i < 4; i++) {
            int y = y8 + i * 8;
            W0T[(size_t)(n0 + y) * KF + (k0 + x)] = __float2half_rn(tile[x][y]);
        }
    }
}

// ---------------- kernel 2: span means (trig + ent) --------------------------
__global__ void spans_kernel(const float* __restrict__ words,
                             const int* __restrict__ tidx,
                             const int* __restrict__ eidx,
                             float* __restrict__ trig,
                             float* __restrict__ ent) {
    int m = blockIdx.x, b = blockIdx.y;
    const int* idx;
    float* out;
    int mm, M;
    if (m < TT) { idx = tidx; out = trig; mm = m; M = TT; }
    else        { idx = eidx; out = ent;  mm = m - TT; M = EE; }
    int s = idx[(b * M + mm) * 2];
    int e = idx[(b * M + mm) * 2 + 1];
    float inv = 1.0f / (float)(e - s);
    const float* base = words + (size_t)b * WW * DD;
    int t = threadIdx.x;
    float a0 = 0.f, a1 = 0.f, a2 = 0.f, a3 = 0.f;
    for (int r = s; r < e; r++) {
        float4 v = ((const float4*)(base + (size_t)r * DD))[t];
        a0 += v.x; a1 += v.y; a2 += v.z; a3 += v.w;
    }
    float4 o = make_float4(a0 * inv, a1 * inv, a2 * inv, a3 * inv);
    ((float4*)(out + (size_t)(b * M + mm) * DD))[t] = o;
}

// ---------------- kernel 3: merged prep = pgemm (60 blocks) + agen (rest) ----
__global__ __launch_bounds__(256)
void prep_kernel(const float* __restrict__ trig,
                 const float* __restrict__ ent,
                 const __half* __restrict__ W0T,
                 const float* __restrict__ b0,
                 float* __restrict__ Pt,
                 float* __restrict__ Pe,
                 __half* __restrict__ A) {
    extern __shared__ char pdsm[];
    int bid = blockIdx.x;
    int tid = threadIdx.x;

    if (bid >= PGEMM_BLOCKS) {
        // ---------------- agen path ----------------
        int bid2 = bid - PGEMM_BLOCKS;
        int b = bid2 >> 10;
        int pair = (bid2 & 1023) * 2 + (tid >> 7);
        int t = pair >> 6, e = pair & 63;
        int lt = tid & 127;
        const float4* tr = (const float4*)(trig + ((size_t)b * TT + t) * DD + lt * 8);
        const float4* er = (const float4*)(ent  + ((size_t)b * EE + e) * DD + lt * 8);
        float4 t0 = tr[0], t1 = tr[1];
        float4 e0 = er[0], e1 = er[1];
        size_t rowo = ((size_t)b * NPAIR + pair) * KP;
        uint4 p;
        p.x = pack_h2(t0.x * e0.x, t0.y * e0.y);
        p.y = pack_h2(t0.z * e0.z, t0.w * e0.w);
        p.z = pack_h2(t1.x * e1.x, t1.y * e1.y);
        p.w = pack_h2(t1.z * e1.z, t1.w * e1.w);
        *(uint4*)(A + rowo + lt * 8) = p;
        uint4 d;
        d.x = pack_h2(fabsf(t0.x - e0.x), fabsf(t0.y - e0.y));
        d.y = pack_h2(fabsf(t0.z - e0.z), fabsf(t0.w - e0.w));
        d.z = pack_h2(fabsf(t1.x - e1.x), fabsf(t1.y - e1.y));
        d.w = pack_h2(fabsf(t1.z - e1.z), fabsf(t1.w - e1.w));
        *(uint4*)(A + rowo + 1024 + lt * 8) = d;
        return;
    }

    // ---------------- pgemm path (double-buffered) ----------------
    uint32_t sb = smem_u32(pdsm);
    int lane = tid & 31, warp = tid >> 5;
    int wm = warp >> 2, wn = warp & 3;
    int g = lane >> 2, t2 = (lane & 3) * 2;
    int nt = bid % NTILES, mtg = bid / NTILES;
    int n0 = nt * 128;

    const float* X;
    float* C;
    const float* bias;
    int m0, koff;
    if (mtg < 4) { X = trig; C = Pt; bias = b0;      m0 = mtg * 128;       koff = 0;  }
    else         { X = ent;  C = Pe; bias = nullptr; m0 = (mtg - 4) * 128; koff = DD; }

    int prow = tid >> 1;
    int cb = (tid & 1) * 32;
    const float* xrow = X + (size_t)(m0 + prow) * DD;
    uint32_t aDst = sb + (uint32_t)prow * PITCH + cb * 2;
    uint32_t bDst = sb + B_OFF + (uint32_t)prow * PITCH + cb * 2;
    const __half* bSrcBase = W0T + (size_t)(n0 + prow) * KF + koff + cb;

    uint32_t aLd = sb + (uint32_t)(wm * 64 + g) * PITCH + (uint32_t)t2 * 2;
    uint32_t bLd = sb + B_OFF + (uint32_t)(wn * 32 + g) * PITCH + (uint32_t)t2 * 2;

    float acc[4][4][4];
#pragma unroll
    for (int i = 0; i < 4; i++)
#pragma unroll
        for (int j = 0; j < 4; j++)
#pragma unroll
            for (int q = 0; q < 4; q++) acc[i][j][q] = 0.f;

    float xv[32];
#pragma unroll
    for (int q = 0; q < 8; q++) {
        float4 v = ((const float4*)(xrow + cb))[q];
        xv[q*4+0] = v.x; xv[q*4+1] = v.y; xv[q*4+2] = v.z; xv[q*4+3] = v.w;
    }
    {
        const char* bs = (const char*)bSrcBase;
#pragma unroll
        for (int q = 0; q < 4; q++)
            cp16(bDst + q * 16, bs + q * 16);
        asm volatile("cp.async.commit_group;" ::: "memory");
    }

    for (int c = 0; c < DD / KC; c++) {
        uint32_t so = (uint32_t)(c & 1) * STAGE_BYTES;
#pragma unroll
        for (int gq = 0; gq < 4; gq++) {
            uint32_t p0 = pack_h2(xv[gq*8+0], xv[gq*8+1]);
            uint32_t p1 = pack_h2(xv[gq*8+2], xv[gq*8+3]);
            uint32_t p2 = pack_h2(xv[gq*8+4], xv[gq*8+5]);
            uint32_t p3 = pack_h2(xv[gq*8+6], xv[gq*8+7]);
            asm volatile("st.shared.v4.b32 [%0], {%1,%2,%3,%4};"
                         :: "r"(aDst + so + gq * 16), "r"(p0), "r"(p1), "r"(p2), "r"(p3) : "memory");
        }
        if (c < DD / KC - 1) {
#pragma unroll
            for (int q = 0; q < 8; q++) {
                float4 v = ((const float4*)(xrow + (c + 1) * KC + cb))[q];
                xv[q*4+0] = v.x; xv[q*4+1] = v.y; xv[q*4+2] = v.z; xv[q*4+3] = v.w;
            }
            uint32_t son = (uint32_t)((c + 1) & 1) * STAGE_BYTES;
            const char* bs = (const char*)(bSrcBase + (c + 1) * KC);
#pragma unroll
            for (int q = 0; q < 4; q++)
                cp16(bDst + son + q * 16, bs + q * 16);
            asm volatile("cp.async.commit_group;" ::: "memory");
            asm volatile("cp.async.wait_group 1;" ::: "memory");
        } else {
            asm volatile("cp.async.wait_group 0;" ::: "memory");
        }
        __syncthreads();
#pragma unroll
        for (int ks = 0; ks < 4; ks++) {
            uint32_t afr[4][4], bfr[4][2];
            uint32_t aO = aLd + so + (uint32_t)ks * 32;
            uint32_t bO = bLd + so + (uint32_t)ks * 32;
#pragma unroll
            for (int j = 0; j < 4; j++) {
                uint32_t o = bO + (uint32_t)j * (8 * PITCH);
                asm volatile("ld.shared.b32 %0, [%1];" : "=r"(bfr[j][0]) : "r"(o));
                asm volatile("ld.shared.b32 %0, [%1];" : "=r"(bfr[j][1]) : "r"(o + 16));
            }
#pragma unroll
            for (int i = 0; i < 4; i++) {
                uint32_t o = aO + (uint32_t)i * (16 * PITCH);
                asm volatile("ld.shared.b32 %0, [%1];" : "=r"(afr[i][0]) : "r"(o));
                asm volatile("ld.shared.b32 %0, [%1];" : "=r"(afr[i][1]) : "r"(o + 8 * PITCH));
                asm volatile("ld.shared.b32 %0, [%1];" : "=r"(afr[i][2]) : "r"(o + 16));
                asm volatile("ld.shared.b32 %0, [%1];" : "=r"(afr[i][3]) : "r"(o + 8 * PITCH + 16));
            }
#pragma unroll
            for (int i = 0; i < 4; i++)
#pragma unroll
                for (int j = 0; j < 4; j++)
                    mma16816(acc[i][j], afr[i], bfr[j]);
        }
        __syncthreads();
    }

#pragma unroll
    for (int j = 0; j < 4; j++) {
        int hcol = n0 + wn * 32 + j * 8 + t2;
#pragma unroll
        for (int cp = 0; cp < 2; cp++) {
            int h = hcol + cp;
            float bb = (bias && h < HH) ? bias[h] : 0.f;
#pragma unroll
            for (int i = 0; i < 4; i++) {
                int r0 = m0 + wm * 64 + i * 16 + g;
                C[(size_t)r0 * NPAD + h]       = acc[i][j][cp] + bb;
                C[(size_t)(r0 + 8) * NPAD + h] = acc[i][j][2 + cp] + bb;
            }
        }
    }
}

// ---------------- kernel 4: pair GEMM (512 thr, x4 B-frags, tail-aware) ------
// grid 1280 1D: bid<1024 -> heavy tiles nt=bid&3, mtb=bid>>2; else light nt=4.
// 2 CTAs/SM, 32 warps/SM, 3-stage cp.async. B fragments: 2 ldmatrix.x4 per ks
// (lane groups address j0/j1 and j2/j3 rows; W0T zero-padded so loads are safe).
__global__ __launch_bounds__(512, 2)
void pair_mma_kernel(const __half* __restrict__ A,
                     const __half* __restrict__ W0T,
                     const float* __restrict__ Pt,
                     const float* __restrict__ Pe,
                     const float* __restrict__ W1,
                     float* __restrict__ part) {
    extern __shared__ char dsm[];
    uint32_t sb = smem_u32(dsm);
    int tid = threadIdx.x;
    int lane = tid & 31, warp = tid >> 5;     // warp 0..15
    int wm = warp >> 2, wn = warp & 3;        // 4 x 4
    int g = lane >> 2, t2 = (lane & 3) * 2;

    int bid = blockIdx.x;
    int nt, mtb;
    if (bid < 1024) { nt = bid & 3; mtb = bid >> 2; }
    else            { nt = 4;       mtb = bid - 1024; }
    int b = mtb >> 4, mt = mtb & 15;
    int n0 = nt * 128;

    // producer: row = tid>>2 (0..127), 32B segment = (tid&3)*32
    int prow = tid >> 2, pseg = tid & 3;
    const char* aSrc = (const char*)A + ((size_t)mtb * 128 + prow) * (KP * 2) + pseg * 32;
    const char* bSrc = (const char*)W0T + ((size_t)(n0 + prow) * KF + KPOFF) * 2 + pseg * 32;
    uint32_t aDst = sb + (uint32_t)prow * PITCH + pseg * 32;
    uint32_t bDst = aDst + B_OFF;

    // ldmatrix lane addressing
    int sub = lane >> 3, r7 = lane & 7;
    // A x4: m0=(rows wm*32+0..7,col0) m1=(+8,col0) m2=(0..7,col16) m3=(+8,col16)
    uint32_t aLdm = sb + (uint32_t)(wm * 32 + (sub & 1) * 8 + r7) * PITCH
                       + (uint32_t)((sub >> 1) * 16);
    // B x4 #1: m0=(j0 rows,col0) m1=(j0,col16) m2=(j1 rows,col0) m3=(j1,col16)
    uint32_t bLdm4 = sb + B_OFF
                        + (uint32_t)(wn * 8 + r7 + (sub >> 1) * 32) * PITCH
                        + (uint32_t)((sub & 1) * 16);

    int nbase_w = n0 + wn * 8;
    int vj0 = nbase_w            < HH;
    int vj1 = nbase_w + 32       < HH;
    int vj2 = nbase_w + 64       < HH;
    int vj3 = nbase_w + 96       < HH;

    float acc[2][4][4];
#pragma unroll
    for (int i = 0; i < 2; i++)
#pragma unroll
        for (int j = 0; j < 4; j++)
#pragma unroll
            for (int q = 0; q < 4; q++) acc[i][j][q] = 0.f;

    // prologue: issue chunks 0,1 into slots 0,1
#pragma unroll
    for (int pc = 0; pc < 2; pc++) {
        uint32_t so = (uint32_t)pc * STAGE_BYTES;
#pragma unroll
        for (int q = 0; q < 2; q++) {
            cp16(aDst + so + q * 16, aSrc + pc * 128 + q * 16);
            cp16(bDst + so + q * 16, bSrc + pc * 128 + q * 16);
        }
        asm volatile("cp.async.commit_group;" ::: "memory");
    }

    for (int c = 0; c < NCHUNK; c++) {
        asm volatile("cp.async.wait_group 1;" ::: "memory");
        __syncthreads();
        int cn = c + 2;
        if (cn < NCHUNK) {
            uint32_t so = (uint32_t)(cn % 3) * STAGE_BYTES;
#pragma unroll
            for (int q = 0; q < 2; q++) {
                cp16(aDst + so + q * 16, aSrc + cn * 128 + q * 16);
                cp16(bDst + so + q * 16, bSrc + cn * 128 + q * 16);
            }
        }
        asm volatile("cp.async.commit_group;" ::: "memory");

        uint32_t stageOff = (uint32_t)(c % 3) * STAGE_BYTES;
#pragma unroll
        for (int ks = 0; ks < 4; ks++) {
            uint32_t afr[2][4], b01[4], b23[4];
            uint32_t aO = aLdm + stageOff + (uint32_t)ks * 32;
            uint32_t bO = bLdm4 + stageOff + (uint32_t)ks * 32;
            ldm_x4(b01, bO);                     // j0 (regs 0,1), j1 (regs 2,3)
            ldm_x4(b23, bO + 64 * PITCH);        // j2, j3
#pragma unroll
            for (int i = 0; i < 2; i++)
                ldm_x4(afr[i], aO + (uint32_t)i * (16 * PITCH));
#pragma unroll
            for (int i = 0; i < 2; i++) {
                if (vj0) mma16816(acc[i][0], afr[i], b01);
                if (vj1) mma16816(acc[i][1], afr[i], b01 + 2);
                if (vj2) mma16816(acc[i][2], afr[i], b23);
                if (vj3) mma16816(acc[i][3], afr[i], b23 + 2);
            }
        }
    }
    __syncthreads();

    // ---- epilogue: acc + Pt + Pe, relu, @W1 -> per-row partials
    float* red = (float*)dsm;  // [128][4][2]
    float pr[2][2][2];
#pragma unroll
    for (int i = 0; i < 2; i++)
#pragma unroll
        for (int hh = 0; hh < 2; hh++) { pr[i][hh][0] = 0.f; pr[i][hh][1] = 0.f; }

    const float* ptRow = Pt + (size_t)(b * TT + 2 * mt + (wm >> 1)) * NPAD;
    const float* peBase = Pe + (size_t)(b * EE) * NPAD;
    int ebase = (wm & 1) * 32;

#pragma unroll
    for (int j = 0; j < 4; j++) {
        int hcol = n0 + j * 32 + wn * 8 + t2;
#pragma unroll
        for (int cp = 0; cp < 2; cp++) {
            int h = hcol + cp;
            if (h < HH) {
                float pt = ptRow[h];
                float w10 = W1[2 * h], w11 = W1[2 * h + 1];
#pragma unroll
                for (int i = 0; i < 2; i++) {
                    float pe0 = peBase[(size_t)(ebase + i * 16 + g) * NPAD + h];
                    float pe1 = peBase[(size_t)(ebase + i * 16 + g + 8) * NPAD + h];
                    float v0 = fmaxf(acc[i][j][cp] + pt + pe0, 0.f);
                    float v1 = fmaxf(acc[i][j][2 + cp] + pt + pe1, 0.f);
                    pr[i][0][0] = fmaf(v0, w10, pr[i][0][0]);
                    pr[i][0][1] = fmaf(v0, w11, pr[i][0][1]);
                    pr[i][1][0] = fmaf(v1, w10, pr[i][1][0]);
                    pr[i][1][1] = fmaf(v1, w11, pr[i][1][1]);
                }
            }
        }
    }
#pragma unroll
    for (int i = 0; i < 2; i++)
#pragma unroll
        for (int hh = 0; hh < 2; hh++)
#pragma unroll
            for (int o = 0; o < 2; o++) {
                float v = pr[i][hh][o];
                v += __shfl_xor_sync(0xffffffffu, v, 1);
                v += __shfl_xor_sync(0xffffffffu, v, 2);
                pr[i][hh][o] = v;
            }
    if ((lane & 3) == 0) {
#pragma unroll
        for (int i = 0; i < 2; i++)
#pragma unroll
            for (int hh = 0; hh < 2; hh++) {
                int row = wm * 32 + i * 16 + g + hh * 8;
                red[(row * 4 + wn) * 2 + 0] = pr[i][hh][0];
                red[(row * 4 + wn) * 2 + 1] = pr[i][hh][1];
            }
    }
    __syncthreads();
    if (tid < 128) {
        int row = tid;
        float a0 = 0.f, a1 = 0.f;
#pragma unroll
        for (int wc = 0; wc < 4; wc++) {
            a0 += red[(row * 4 + wc) * 2 + 0];
            a1 += red[(row * 4 + wc) * 2 + 1];
        }
        int pair = (2 * mt + (row >> 6)) * EE + (row & 63);
        size_t oidx = ((size_t)nt * BB * NPAIR + (size_t)b * NPAIR + pair) * 2;
        part[oidx]     = a0;
        part[oidx + 1] = a1;
    }
}

// ---------------- kernel 5: reduce 5 partials + b1 ---------------------------
__global__ void reduce_out_kernel(const float* __restrict__ part,
                                  const float* __restrict__ b1,
                                  float* __restrict__ out) {
    int i = blockIdx.x * blockDim.x + threadIdx.x;
    float a = b1[i & 1];
#pragma unroll
    for (int t = 0; t < NTILES; t++)
        a += part[(size_t)t * BB * NPAIR * 2 + i];
    out[i] = a;
}

// ---------------- launch -----------------------------------------------------
extern "C" void kernel_launch(void* const* d_in, const int* in_sizes, int n_in,
                              void* d_out, int out_size) {
    const float* piece = (const float*)d_in[0];
    const int*   widx  = (const int*)d_in[1];
    const int*   tidx  = (const int*)d_in[2];
    const int*   eidx  = (const int*)d_in[3];
    const float* W0    = (const float*)d_in[4];
    const float* b0    = (const float*)d_in[5];
    const float* W1    = (const float*)d_in[6];
    const float* b1    = (const float*)d_in[7];
    float* out = (float*)d_out;

    float *wordp, *trigp, *entp, *ptp, *pep, *partp;
    __half *w0tp, *ap;
    cudaGetSymbolAddress((void**)&wordp, g_word);
    cudaGetSymbolAddress((void**)&trigp, g_trig);
    cudaGetSymbolAddress((void**)&entp,  g_ent);
    cudaGetSymbolAddress((void**)&w0tp,  g_W0T);
    cudaGetSymbolAddress((void**)&ap,    g_A);
    cudaGetSymbolAddress((void**)&ptp,   g_Pt);
    cudaGetSymbolAddress((void**)&pep,   g_Pe);
    cudaGetSymbolAddress((void**)&partp, g_part);

    cudaFuncSetAttribute(pair_mma_kernel,
                         cudaFuncAttributeMaxDynamicSharedMemorySize, SMEM_DYN);
    cudaFuncSetAttribute(prep_kernel,
                         cudaFuncAttributeMaxDynamicSharedMemorySize, PGEMM_SMEM);

    word_bprep_kernel<<<NWORD + (KF / 32) * (NPAD / 32), 256>>>(
        piece, widx, W0, wordp, w0tp);
    spans_kernel<<<dim3(TT + EE, BB), 256>>>(wordp, tidx, eidx, trigp, entp);
    prep_kernel<<<PGEMM_BLOCKS + (NPAIR / 2) * BB, 256, PGEMM_SMEM>>>(
        trigp, entp, w0tp, b0, ptp, pep, ap);
    pair_mma_kernel<<<NTILES * 256, 512, SMEM_DYN>>>(
        ap, w0tp, ptp, pep, W1, partp);
    reduce_out_kernel<<<(BB * NPAIR * 2) / 1024, 1024>>>(partp, b1, out);
    (void)in_sizes; (void)n_in; (void)out_size;
}

// round 16
// speedup vs baseline: 1.3121x; 1.0180x over previous
#include <cuda_runtime.h>
#include <cuda_fp16.h>
#include <math.h>
#include <stdint.h>

// Problem constants
#define BB 16
#define PP 512
#define DD 1024
#define WW 400
#define TT 32
#define EE 64
#define HH 600
#define NPAIR (TT * EE)     // 2048
#define KF 4096             // W0T row length
#define KPOFF 2048          // pair-GEMM feature base: [t*e | |t-e|]
#define KP 2048             // pair-GEMM K
#define NPAD 640
#define KC 64               // k per chunk
#define NCHUNK 32           // KP / KC
#define NTILES 5            // h tiles of 128

// smem geometry (bytes): stage = A[128][64h] + B[128][64h], pitch 144
#define PITCH 144
#define B_OFF (128 * PITCH)               // 18432
#define STAGE_BYTES (2 * 128 * PITCH)     // 36864
#define NSTAGE 3
#define SMEM_DYN (NSTAGE * STAGE_BYTES)   // 110592
#define PGEMM_SMEM (2 * STAGE_BYTES)      // 73728
#define PGEMM_BLOCKS (NTILES * 12)        // 60
#define NSPAN ((TT + EE) * BB)            // 1536

// ---------------- scratch ----------------------------------------------------
__device__ float g_trig[(size_t)BB * TT * DD];
__device__ float g_ent [(size_t)BB * EE * DD];
__device__ __half g_W0T[(size_t)NPAD * KF];            // W0^T fp16 [n][k]
__device__ __half g_A  [(size_t)BB * NPAIR * KP];      // pair features fp16 (134MB)
__device__ float g_Pt [(size_t)BB * TT * NPAD];
__device__ float g_Pe [(size_t)BB * EE * NPAD];
__device__ float g_part[(size_t)NTILES * BB * NPAIR * 2];

// ---------------- helpers ----------------------------------------------------
__device__ __forceinline__ void mma16816(float* c, const uint32_t* a, const uint32_t* b) {
    asm volatile(
        "mma.sync.aligned.m16n8k16.row.col.f32.f16.f16.f32 "
        "{%0,%1,%2,%3}, {%4,%5,%6,%7}, {%8,%9}, {%0,%1,%2,%3};"
        : "+f"(c[0]), "+f"(c[1]), "+f"(c[2]), "+f"(c[3])
        : "r"(a[0]), "r"(a[1]), "r"(a[2]), "r"(a[3]), "r"(b[0]), "r"(b[1]));
}
__device__ __forceinline__ void ldm_x4(uint32_t* r, uint32_t addr) {
    asm volatile("ldmatrix.sync.aligned.m8n8.x4.shared.b16 {%0,%1,%2,%3}, [%4];"
                 : "=r"(r[0]), "=r"(r[1]), "=r"(r[2]), "=r"(r[3]) : "r"(addr));
}
__device__ __forceinline__ void cp16(uint32_t dst, const void* src) {
    asm volatile("cp.async.ca.shared.global [%0], [%1], 16;" :: "r"(dst), "l"(src) : "memory");
}
__device__ __forceinline__ uint32_t smem_u32(const void* p) {
    uint32_t a;
    asm("{ .reg .u64 t; cvta.to.shared.u64 t, %1; cvt.u32.u64 %0, t; }"
        : "=r"(a) : "l"(p));
    return a;
}
__device__ __forceinline__ uint32_t pack_h2(float lo, float hi) {
    uint32_t r;
    asm("cvt.rn.f16x2.f32 %0, %1, %2;" : "=r"(r) : "f"(hi), "f"(lo));
    return r;
}

// ---------------- kernel 1: fused span means (direct from piece) + bprep -----
// blocks [0,NSPAN): span means. Per span, iterate its words; each word's mean
// computed inline with the same FP order as the old two-stage path (sequential
// piece-row adds -> *inv_word_len -> sequential word adds -> *inv_span_len),
// so results are bit-identical. blocks [NSPAN, +2560): W0 -> W0T fp16.
__global__ void spans_bprep_kernel(const float* __restrict__ piece,
                                   const int* __restrict__ widx,
                                   const int* __restrict__ tidx,
                                   const int* __restrict__ eidx,
                                   const float* __restrict__ W0,
                                   float* __restrict__ trig,
                                   float* __restrict__ ent,
                                   __half* __restrict__ W0T) {
    __shared__ float tile[32][33];
    int bid = blockIdx.x;
    if (bid < NSPAN) {
        int m = bid % (TT + EE), b = bid / (TT + EE);
        const int* idx;
        float* out;
        int mm, M;
        if (m < TT) { idx = tidx; out = trig; mm = m; M = TT; }
        else        { idx = eidx; out = ent;  mm = m - TT; M = EE; }
        int s = idx[(b * M + mm) * 2];
        int e = idx[(b * M + mm) * 2 + 1];
        float inv = 1.0f / (float)(e - s);
        const float* base = piece + (size_t)b * PP * DD;
        const int* wbase = widx + b * WW * 2;
        int t = threadIdx.x;
        float a0 = 0.f, a1 = 0.f, a2 = 0.f, a3 = 0.f;
        for (int w = s; w < e; w++) {
            int ps = wbase[w * 2], pe = wbase[w * 2 + 1];
            float winv = 1.0f / (float)(pe - ps);
            float w0 = 0.f, w1 = 0.f, w2 = 0.f, w3 = 0.f;
            for (int r = ps; r < pe; r++) {
                float4 v = ((const float4*)(base + (size_t)r * DD))[t];
                w0 += v.x; w1 += v.y; w2 += v.z; w3 += v.w;
            }
            a0 += w0 * winv; a1 += w1 * winv; a2 += w2 * winv; a3 += w3 * winv;
        }
        float4 o = make_float4(a0 * inv, a1 * inv, a2 * inv, a3 * inv);
        ((float4*)(out + (size_t)(b * M + mm) * DD))[t] = o;
    } else {
        int b2 = bid - NSPAN;               // 0..2559
        int k0 = (b2 & 127) * 32;
        int n0 = (b2 >> 7) * 32;
        int x = threadIdx.x & 31, y8 = threadIdx.x >> 5;
#pragma unroll
        for (int i = 0; i < 4; i++) {
            int y = y8 + i * 8;
            float v = 0.f;
            if (n0 + x < HH) v = W0[(size_t)(k0 + y) * HH + (n0 + x)];
            tile[y][x] = v;
        }
        __syncthreads();
#pragma unroll
        for (int i = 0; i < 4; i++) {
            int y = y8 + i * 8;
            W0T[(size_t)(n0 + y) * KF + (k0 + x)] = __float2half_rn(tile[x][y]);
        }
    }
}

// ---------------- kernel 2: merged prep = pgemm (60 blocks) + agen (rest) ----
__global__ __launch_bounds__(256)
void prep_kernel(const float* __restrict__ trig,
                 const float* __restrict__ ent,
                 const __half* __restrict__ W0T,
                 const float* __restrict__ b0,
                 float* __restrict__ Pt,
                 float* __restrict__ Pe,
                 __half* __restrict__ A) {
    extern __shared__ char pdsm[];
    int bid = blockIdx.x;
    int tid = threadIdx.x;

    if (bid >= PGEMM_BLOCKS) {
        // ---------------- agen path ----------------
        int bid2 = bid - PGEMM_BLOCKS;
        int b = bid2 >> 10;
        int pair = (bid2 & 1023) * 2 + (tid >> 7);
        int t = pair >> 6, e = pair & 63;
        int lt = tid & 127;
        const float4* tr = (const float4*)(trig + ((size_t)b * TT + t) * DD + lt * 8);
        const float4* er = (const float4*)(ent  + ((size_t)b * EE + e) * DD + lt * 8);
        float4 t0 = tr[0], t1 = tr[1];
        float4 e0 = er[0], e1 = er[1];
        size_t rowo = ((size_t)b * NPAIR + pair) * KP;
        uint4 p;
        p.x = pack_h2(t0.x * e0.x, t0.y * e0.y);
        p.y = pack_h2(t0.z * e0.z, t0.w * e0.w);
        p.z = pack_h2(t1.x * e1.x, t1.y * e1.y);
        p.w = pack_h2(t1.z * e1.z, t1.w * e1.w);
        *(uint4*)(A + rowo + lt * 8) = p;
        uint4 d;
        d.x = pack_h2(fabsf(t0.x - e0.x), fabsf(t0.y - e0.y));
        d.y = pack_h2(fabsf(t0.z - e0.z), fabsf(t0.w - e0.w));
        d.z = pack_h2(fabsf(t1.x - e1.x), fabsf(t1.y - e1.y));
        d.w = pack_h2(fabsf(t1.z - e1.z), fabsf(t1.w - e1.w));
        *(uint4*)(A + rowo + 1024 + lt * 8) = d;
        return;
    }

    // ---------------- pgemm path (double-buffered) ----------------
    uint32_t sb = smem_u32(pdsm);
    int lane = tid & 31, warp = tid >> 5;
    int wm = warp >> 2, wn = warp & 3;
    int g = lane >> 2, t2 = (lane & 3) * 2;
    int nt = bid % NTILES, mtg = bid / NTILES;
    int n0 = nt * 128;

    const float* X;
    float* C;
    const float* bias;
    int m0, koff;
    if (mtg < 4) { X = trig; C = Pt; bias = b0;      m0 = mtg * 128;       koff = 0;  }
    else         { X = ent;  C = Pe; bias = nullptr; m0 = (mtg - 4) * 128; koff = DD; }

    int prow = tid >> 1;
    int cb = (tid & 1) * 32;
    const float* xrow = X + (size_t)(m0 + prow) * DD;
    uint32_t aDst = sb + (uint32_t)prow * PITCH + cb * 2;
    uint32_t bDst = sb + B_OFF + (uint32_t)prow * PITCH + cb * 2;
    const __half* bSrcBase = W0T + (size_t)(n0 + prow) * KF + koff + cb;

    uint32_t aLd = sb + (uint32_t)(wm * 64 + g) * PITCH + (uint32_t)t2 * 2;
    uint32_t bLd = sb + B_OFF + (uint32_t)(wn * 32 + g) * PITCH + (uint32_t)t2 * 2;

    float acc[4][4][4];
#pragma unroll
    for (int i = 0; i < 4; i++)
#pragma unroll
        for (int j = 0; j < 4; j++)
#pragma unroll
            for (int q = 0; q < 4; q++) acc[i][j][q] = 0.f;

    float xv[32];
#pragma unroll
    for (int q = 0; q < 8; q++) {
        float4 v = ((const float4*)(xrow + cb))[q];
        xv[q*4+0] = v.x; xv[q*4+1] = v.y; xv[q*4+2] = v.z; xv[q*4+3] = v.w;
    }
    {
        const char* bs = (const char*)bSrcBase;
#pragma unroll
        for (int q = 0; q < 4; q++)
            cp16(bDst + q * 16, bs + q * 16);
        asm volatile("cp.async.commit_group;" ::: "memory");
    }

    for (int c = 0; c < DD / KC; c++) {
        uint32_t so = (uint32_t)(c & 1) * STAGE_BYTES;
#pragma unroll
        for (int gq = 0; gq < 4; gq++) {
            uint32_t p0 = pack_h2(xv[gq*8+0], xv[gq*8+1]);
            uint32_t p1 = pack_h2(xv[gq*8+2], xv[gq*8+3]);
            uint32_t p2 = pack_h2(xv[gq*8+4], xv[gq*8+5]);
            uint32_t p3 = pack_h2(xv[gq*8+6], xv[gq*8+7]);
            asm volatile("st.shared.v4.b32 [%0], {%1,%2,%3,%4};"
                         :: "r"(aDst + so + gq * 16), "r"(p0), "r"(p1), "r"(p2), "r"(p3) : "memory");
        }
        if (c < DD / KC - 1) {
#pragma unroll
            for (int q = 0; q < 8; q++) {
                float4 v = ((const float4*)(xrow + (c + 1) * KC + cb))[q];
                xv[q*4+0] = v.x; xv[q*4+1] = v.y; xv[q*4+2] = v.z; xv[q*4+3] = v.w;
            }
            uint32_t son = (uint32_t)((c + 1) & 1) * STAGE_BYTES;
            const char* bs = (const char*)(bSrcBase + (c + 1) * KC);
#pragma unroll
            for (int q = 0; q < 4; q++)
                cp16(bDst + son + q * 16, bs + q * 16);
            asm volatile("cp.async.commit_group;" ::: "memory");
            asm volatile("cp.async.wait_group 1;" ::: "memory");
        } else {
            asm volatile("cp.async.wait_group 0;" ::: "memory");
        }
        __syncthreads();
#pragma unroll
        for (int ks = 0; ks < 4; ks++) {
            uint32_t afr[4][4], bfr[4][2];
            uint32_t aO = aLd + so + (uint32_t)ks * 32;
            uint32_t bO = bLd + so + (uint32_t)ks * 32;
#pragma unroll
            for (int j = 0; j < 4; j++) {
                uint32_t o = bO + (uint32_t)j * (8 * PITCH);
                asm volatile("ld.shared.b32 %0, [%1];" : "=r"(bfr[j][0]) : "r"(o));
                asm volatile("ld.shared.b32 %0, [%1];" : "=r"(bfr[j][1]) : "r"(o + 16));
            }
#pragma unroll
            for (int i = 0; i < 4; i++) {
                uint32_t o = aO + (uint32_t)i * (16 * PITCH);
                asm volatile("ld.shared.b32 %0, [%1];" : "=r"(afr[i][0]) : "r"(o));
                asm volatile("ld.shared.b32 %0, [%1];" : "=r"(afr[i][1]) : "r"(o + 8 * PITCH));
                asm volatile("ld.shared.b32 %0, [%1];" : "=r"(afr[i][2]) : "r"(o + 16));
                asm volatile("ld.shared.b32 %0, [%1];" : "=r"(afr[i][3]) : "r"(o + 8 * PITCH + 16));
            }
#pragma unroll
            for (int i = 0; i < 4; i++)
#pragma unroll
                for (int j = 0; j < 4; j++)
                    mma16816(acc[i][j], afr[i], bfr[j]);
        }
        __syncthreads();
    }

#pragma unroll
    for (int j = 0; j < 4; j++) {
        int hcol = n0 + wn * 32 + j * 8 + t2;
#pragma unroll
        for (int cp = 0; cp < 2; cp++) {
            int h = hcol + cp;
            float bb = (bias && h < HH) ? bias[h] : 0.f;
#pragma unroll
            for (int i = 0; i < 4; i++) {
                int r0 = m0 + wm * 64 + i * 16 + g;
                C[(size_t)r0 * NPAD + h]       = acc[i][j][cp] + bb;
                C[(size_t)(r0 + 8) * NPAD + h] = acc[i][j][2 + cp] + bb;
            }
        }
    }
}

// ---------------- kernel 3: pair GEMM (512 thr, x4 B-frags, tail-aware) ------
__global__ __launch_bounds__(512, 2)
void pair_mma_kernel(const __half* __restrict__ A,
                     const __half* __restrict__ W0T,
                     const float* __restrict__ Pt,
                     const float* __restrict__ Pe,
                     const float* __restrict__ W1,
                     float* __restrict__ part) {
    extern __shared__ char dsm[];
    uint32_t sb = smem_u32(dsm);
    int tid = threadIdx.x;
    int lane = tid & 31, warp = tid >> 5;     // warp 0..15
    int wm = warp >> 2, wn = warp & 3;        // 4 x 4
    int g = lane >> 2, t2 = (lane & 3) * 2;

    int bid = blockIdx.x;
    int nt, mtb;
    if (bid < 1024) { nt = bid & 3; mtb = bid >> 2; }
    else            { nt = 4;       mtb = bid - 1024; }
    int b = mtb >> 4, mt = mtb & 15;
    int n0 = nt * 128;

    int prow = tid >> 2, pseg = tid & 3;
    const char* aSrc = (const char*)A + ((size_t)mtb * 128 + prow) * (KP * 2) + pseg * 32;
    const char* bSrc = (const char*)W0T + ((size_t)(n0 + prow) * KF + KPOFF) * 2 + pseg * 32;
    uint32_t aDst = sb + (uint32_t)prow * PITCH + pseg * 32;
    uint32_t bDst = aDst + B_OFF;

    int sub = lane >> 3, r7 = lane & 7;
    uint32_t aLdm = sb + (uint32_t)(wm * 32 + (sub & 1) * 8 + r7) * PITCH
                       + (uint32_t)((sub >> 1) * 16);
    uint32_t bLdm4 = sb + B_OFF
                        + (uint32_t)(wn * 8 + r7 + (sub >> 1) * 32) * PITCH
                        + (uint32_t)((sub & 1) * 16);

    int nbase_w = n0 + wn * 8;
    int vj0 = nbase_w            < HH;
    int vj1 = nbase_w + 32       < HH;
    int vj2 = nbase_w + 64       < HH;
    int vj3 = nbase_w + 96       < HH;

    float acc[2][4][4];
#pragma unroll
    for (int i = 0; i < 2; i++)
#pragma unroll
        for (int j = 0; j < 4; j++)
#pragma unroll
            for (int q = 0; q < 4; q++) acc[i][j][q] = 0.f;

#pragma unroll
    for (int pc = 0; pc < 2; pc++) {
        uint32_t so = (uint32_t)pc * STAGE_BYTES;
#pragma unroll
        for (int q = 0; q < 2; q++) {
            cp16(aDst + so + q * 16, aSrc + pc * 128 + q * 16);
            cp16(bDst + so + q * 16, bSrc + pc * 128 + q * 16);
        }
        asm volatile("cp.async.commit_group;" ::: "memory");
    }

    for (int c = 0; c < NCHUNK; c++) {
        asm volatile("cp.async.wait_group 1;" ::: "memory");
        __syncthreads();
        int cn = c + 2;
        if (cn < NCHUNK) {
            uint32_t so = (uint32_t)(cn % 3) * STAGE_BYTES;
#pragma unroll
            for (int q = 0; q < 2; q++) {
                cp16(aDst + so + q * 16, aSrc + cn * 128 + q * 16);
                cp16(bDst + so + q * 16, bSrc + cn * 128 + q * 16);
            }
        }
        asm volatile("cp.async.commit_group;" ::: "memory");

        uint32_t stageOff = (uint32_t)(c % 3) * STAGE_BYTES;
#pragma unroll
        for (int ks = 0; ks < 4; ks++) {
            uint32_t afr[2][4], b01[4], b23[4];
            uint32_t aO = aLdm + stageOff + (uint32_t)ks * 32;
            uint32_t bO = bLdm4 + stageOff + (uint32_t)ks * 32;
            ldm_x4(b01, bO);
            ldm_x4(b23, bO + 64 * PITCH);
#pragma unroll
            for (int i = 0; i < 2; i++)
                ldm_x4(afr[i], aO + (uint32_t)i * (16 * PITCH));
#pragma unroll
            for (int i = 0; i < 2; i++) {
                if (vj0) mma16816(acc[i][0], afr[i], b01);
                if (vj1) mma16816(acc[i][1], afr[i], b01 + 2);
                if (vj2) mma16816(acc[i][2], afr[i], b23);
                if (vj3) mma16816(acc[i][3], afr[i], b23 + 2);
            }
        }
    }
    __syncthreads();

    float* red = (float*)dsm;
    float pr[2][2][2];
#pragma unroll
    for (int i = 0; i < 2; i++)
#pragma unroll
        for (int hh = 0; hh < 2; hh++) { pr[i][hh][0] = 0.f; pr[i][hh][1] = 0.f; }

    const float* ptRow = Pt + (size_t)(b * TT + 2 * mt + (wm >> 1)) * NPAD;
    const float* peBase = Pe + (size_t)(b * EE) * NPAD;
    int ebase = (wm & 1) * 32;

#pragma unroll
    for (int j = 0; j < 4; j++) {
        int hcol = n0 + j * 32 + wn * 8 + t2;
#pragma unroll
        for (int cp = 0; cp < 2; cp++) {
            int h = hcol + cp;
            if (h < HH) {
                float pt = ptRow[h];
                float w10 = W1[2 * h], w11 = W1[2 * h + 1];
#pragma unroll
                for (int i = 0; i < 2; i++) {
                    float pe0 = peBase[(size_t)(ebase + i * 16 + g) * NPAD + h];
                    float pe1 = peBase[(size_t)(ebase + i * 16 + g + 8) * NPAD + h];
                    float v0 = fmaxf(acc[i][j][cp] + pt + pe0, 0.f);
                    float v1 = fmaxf(acc[i][j][2 + cp] + pt + pe1, 0.f);
                    pr[i][0][0] = fmaf(v0, w10, pr[i][0][0]);
                    pr[i][0][1] = fmaf(v0, w11, pr[i][0][1]);
                    pr[i][1][0] = fmaf(v1, w10, pr[i][1][0]);
                    pr[i][1][1] = fmaf(v1, w11, pr[i][1][1]);
                }
            }
        }
    }
#pragma unroll
    for (int i = 0; i < 2; i++)
#pragma unroll
        for (int hh = 0; hh < 2; hh++)
#pragma unroll
            for (int o = 0; o < 2; o++) {
                float v = pr[i][hh][o];
                v += __shfl_xor_sync(0xffffffffu, v, 1);
                v += __shfl_xor_sync(0xffffffffu, v, 2);
                pr[i][hh][o] = v;
            }
    if ((lane & 3) == 0) {
#pragma unroll
        for (int i = 0; i < 2; i++)
#pragma unroll
            for (int hh = 0; hh < 2; hh++) {
                int row = wm * 32 + i * 16 + g + hh * 8;
                red[(row * 4 + wn) * 2 + 0] = pr[i][hh][0];
                red[(row * 4 + wn) * 2 + 1] = pr[i][hh][1];
            }
    }
    __syncthreads();
    if (tid < 128) {
        int row = tid;
        float a0 = 0.f, a1 = 0.f;
#pragma unroll
        for (int wc = 0; wc < 4; wc++) {
            a0 += red[(row * 4 + wc) * 2 + 0];
            a1 += red[(row * 4 + wc) * 2 + 1];
        }
        int pair = (2 * mt + (row >> 6)) * EE + (row & 63);
        size_t oidx = ((size_t)nt * BB * NPAIR + (size_t)b * NPAIR + pair) * 2;
        part[oidx]     = a0;
        part[oidx + 1] = a1;
    }
}

// ---------------- kernel 4: reduce 5 partials + b1 ---------------------------
__global__ void reduce_out_kernel(const float* __restrict__ part,
                                  const float* __restrict__ b1,
                                  float* __restrict__ out) {
    int i = blockIdx.x * blockDim.x + threadIdx.x;
    float a = b1[i & 1];
#pragma unroll
    for (int t = 0; t < NTILES; t++)
        a += part[(size_t)t * BB * NPAIR * 2 + i];
    out[i] = a;
}

// ---------------- launch -----------------------------------------------------
extern "C" void kernel_launch(void* const* d_in, const int* in_sizes, int n_in,
                              void* d_out, int out_size) {
    const float* piece = (const float*)d_in[0];
    const int*   widx  = (const int*)d_in[1];
    const int*   tidx  = (const int*)d_in[2];
    const int*   eidx  = (const int*)d_in[3];
    const float* W0    = (const float*)d_in[4];
    const float* b0    = (const float*)d_in[5];
    const float* W1    = (const float*)d_in[6];
    const float* b1    = (const float*)d_in[7];
    float* out = (float*)d_out;

    float *trigp, *entp, *ptp, *pep, *partp;
    __half *w0tp, *ap;
    cudaGetSymbolAddress((void**)&trigp, g_trig);
    cudaGetSymbolAddress((void**)&entp,  g_ent);
    cudaGetSymbolAddress((void**)&w0tp,  g_W0T);
    cudaGetSymbolAddress((void**)&ap,    g_A);
    cudaGetSymbolAddress((void**)&ptp,   g_Pt);
    cudaGetSymbolAddress((void**)&pep,   g_Pe);
    cudaGetSymbolAddress((void**)&partp, g_part);

    cudaFuncSetAttribute(pair_mma_kernel,
                         cudaFuncAttributeMaxDynamicSharedMemorySize, SMEM_DYN);
    cudaFuncSetAttribute(prep_kernel,
                         cudaFuncAttributeMaxDynamicSharedMemorySize, PGEMM_SMEM);

    spans_bprep_kernel<<<NSPAN + (KF / 32) * (NPAD / 32), 256>>>(
        piece, widx, tidx, eidx, W0, trigp, entp, w0tp);
    prep_kernel<<<PGEMM_BLOCKS + (NPAIR / 2) * BB, 256, PGEMM_SMEM>>>(
        trigp, entp, w0tp, b0, ptp, pep, ap);
    pair_mma_kernel<<<NTILES * 256, 512, SMEM_DYN>>>(
        ap, w0tp, ptp, pep, W1, partp);
    reduce_out_kernel<<<(BB * NPAIR * 2) / 1024, 1024>>>(partp, b1, out);
    (void)in_sizes; (void)n_in; (void)out_size;
}